// round 13
// baseline (speedup 1.0000x reference)
#include <cuda_runtime.h>
#include <math.h>
#include <stdint.h>

#define Nn 20000
#define Ff 32
#define Tt 12
#define Hh 64
#define Ee 320000
#define OUTD 12
#define TN (Tt * Nn)
#define GB 313

#if defined(__CUDA_ARCH__) && __CUDA_ARCH__ >= 900
#define PDL_SYNC()    cudaGridDependencySynchronize()
#define PDL_TRIGGER() cudaTriggerProgrammaticLaunchCompletion()
#else
#define PDL_SYNC()
#define PDL_TRIGGER()
#endif

// ---------------- scratch ----------------
static __device__ float g_xt[(size_t)TN * Ff];
static __device__ float g_deg[Nn];
static __device__ float g_dinv[Nn];
static __device__ int   g_cnt[Nn];
static __device__ int   g_cur[Nn];
static __device__ int   g_rowptr[Nn + 1];
static __device__ int   g_csrsrc[Ee];
static __device__ float g_csrnorm[Ee];
static __device__ float g_xw0all[(size_t)TN * Hh];
static __device__ float g_g0all[(size_t)TN * Hh];
static __device__ float g_p0all[(size_t)TN * 192];
static __device__ float g_xw[(size_t)Nn * Hh];
static __device__ float g_gg[(size_t)Nn * Hh];
static __device__ float g_h0[(size_t)Nn * Hh];
static __device__ float g_h1[(size_t)Nn * Hh];
static __device__ float g_hseq[(size_t)TN * Hh];
static __device__ float g_qkv[(size_t)TN * 192];
static __device__ float g_ipwT[Hh * 192];
static __device__ float g_opwT[Hh * Hh];

// unified pre-packed tf32 b-fragments: 42 chunks x 2048 unsigned
static __device__ unsigned g_pkall[42 * 2048];
#define PK_WG0  0
#define PK_PRE0 1
#define PK_URC0 10
#define PK_WG1  16
#define PK_URC1 18
#define PK_QKV  36

struct PackTab { const float* src[42]; int ldw[42]; };

__device__ __forceinline__ float sigmoidf_(float x) { return 1.0f / (1.0f + __expf(-x)); }

__device__ __forceinline__ unsigned f2tf32(float f) {
    unsigned r;
    asm("cvt.rna.tf32.f32 %0, %1;" : "=r"(r) : "f"(f));
    return r;
}

__device__ __forceinline__ void mma_tf32(float c[4], const unsigned a[4], unsigned b0, unsigned b1) {
    asm volatile(
        "mma.sync.aligned.m16n8k8.row.col.f32.tf32.tf32.f32 "
        "{%0,%1,%2,%3}, {%4,%5,%6,%7}, {%8,%9}, {%0,%1,%2,%3};"
        : "+f"(c[0]), "+f"(c[1]), "+f"(c[2]), "+f"(c[3])
        : "r"(a[0]), "r"(a[1]), "r"(a[2]), "r"(a[3]), "r"(b0), "r"(b1));
}

__device__ __forceinline__ void load_A_raw(float x[16], const float* __restrict__ A,
                                           int lda, int r0, int r1, bool v0, bool v1,
                                           int k0, int qc) {
#pragma unroll
    for (int s = 0; s < 4; s++) {
        int k = k0 + 8 * s + qc;
        x[4 * s + 0] = v0 ? A[(size_t)r0 * lda + k] : 0.f;
        x[4 * s + 1] = v1 ? A[(size_t)r1 * lda + k] : 0.f;
        x[4 * s + 2] = v0 ? A[(size_t)r0 * lda + k + 4] : 0.f;
        x[4 * s + 3] = v1 ? A[(size_t)r1 * lda + k + 4] : 0.f;
    }
}

__device__ __forceinline__ void cvt_frag(unsigned a[4][4], const float x[16]) {
#pragma unroll
    for (int s = 0; s < 4; s++)
#pragma unroll
        for (int j = 0; j < 4; j++) a[s][j] = f2tf32(x[4 * s + j]);
}

__device__ __forceinline__ void load_A_chunk(unsigned a[4][4], const float* __restrict__ A,
                                             int lda, int r0, int r1, bool v0, bool v1,
                                             int k0, int qc) {
    float x[16];
    load_A_raw(x, A, lda, r0, r1, v0, v1, k0, qc);
    cvt_frag(a, x);
}

__device__ __forceinline__ void load_A_smemU(unsigned a[4][4], const unsigned* U,
                                             int rl0, int k0, int qc) {
#pragma unroll
    for (int s = 0; s < 4; s++) {
        int k = k0 + 8 * s + qc;
        a[s][0] = U[k * 72 + rl0];
        a[s][1] = U[k * 72 + rl0 + 8];
        a[s][2] = U[(k + 4) * 72 + rl0];
        a[s][3] = U[(k + 4) * 72 + rl0 + 8];
    }
}

__device__ __forceinline__ void mma_gate(float C[8][4], const unsigned a[4][4],
                                         const unsigned* __restrict__ Bpk, int lane) {
    const uint4* B4 = (const uint4*)Bpk;
#pragma unroll
    for (int s = 0; s < 4; s++)
#pragma unroll
        for (int f2 = 0; f2 < 4; f2++) {
            uint4 b = B4[(s * 4 + f2) * 32 + lane];
            mma_tf32(C[2 * f2], a[s], b.x, b.y);
            mma_tf32(C[2 * f2 + 1], a[s], b.z, b.w);
        }
}

// ---------------- single-launch weight pack ----------------------------------
__global__ void k_packall(PackTab tab) {
    int tid = blockIdx.x * blockDim.x + threadIdx.x;
    if (tid >= 42 * 512) return;
    int g = tid >> 9, r = tid & 511;
    const float* W = tab.src[g];
    int ldw = tab.ldw[g];
    int s = r >> 7, f2 = (r >> 5) & 3, lane = r & 31;
    int qr = lane >> 2, qc = lane & 3;
    int k1 = 8 * s + qc, k2 = k1 + 4;
    int n1 = 16 * f2 + qr, n2 = n1 + 8;
    uint4 o;
    o.x = f2tf32(W[(size_t)k1 * ldw + n1]);
    o.y = f2tf32(W[(size_t)k2 * ldw + n1]);
    o.z = f2tf32(W[(size_t)k1 * ldw + n2]);
    o.w = f2tf32(W[(size_t)k2 * ldw + n2]);
    ((uint4*)g_pkall)[tid] = o;
}

// ---------------- preprocessing ----------------
__global__ void k_transpose(const float* __restrict__ x) {
    int idx = blockIdx.x * blockDim.x + threadIdx.x;
    if (idx >= Nn * Ff * Tt) return;
    int f = idx & (Ff - 1);
    int t = (idx / Ff) % Tt;
    int n = idx / (Ff * Tt);
    g_xt[(size_t)t * Nn * Ff + (size_t)n * Ff + f] = x[(size_t)n * Ff * Tt + (size_t)f * Tt + t];
}

__global__ void k_trW(const float* __restrict__ ipw, const float* __restrict__ opw) {
    int i = blockIdx.x * blockDim.x + threadIdx.x;
    if (i < 192 * Hh) { int r = i / Hh, c = i % Hh; g_ipwT[c * 192 + r] = ipw[i]; }
    if (i < Hh * Hh)  { int r = i / Hh, c = i % Hh; g_opwT[c * Hh + r] = opw[i]; }
}

__global__ void k_deg_hist(const int* __restrict__ ei, const float* __restrict__ ea) {
    int e = blockIdx.x * blockDim.x + threadIdx.x;
    if (e >= Ee) return;
    int d = ei[Ee + e];
    atomicAdd(&g_deg[d], ea[2 * e + 1]);
    atomicAdd(&g_cnt[d], 1);
}

// scan + fused dinv
__global__ void k_scan() {
    __shared__ int sbuf[1024];
    __shared__ int s_carry;
    int tid = threadIdx.x;
    if (tid == 0) { s_carry = 0; g_rowptr[0] = 0; }
    __syncthreads();
    for (int base = 0; base < Nn; base += 1024) {
        int v = (base + tid < Nn) ? g_cnt[base + tid] : 0;
        sbuf[tid] = v;
        __syncthreads();
        for (int off = 1; off < 1024; off <<= 1) {
            int t2 = (tid >= off) ? sbuf[tid - off] : 0;
            __syncthreads();
            sbuf[tid] += t2;
            __syncthreads();
        }
        int incl = sbuf[tid] + s_carry;
        if (base + tid < Nn) g_rowptr[base + tid + 1] = incl;
        int total = sbuf[1023];
        __syncthreads();
        if (tid == 0) s_carry += total;
        __syncthreads();
    }
    for (int n = tid; n < Nn; n += 1024)
        g_dinv[n] = rsqrtf(g_deg[n] + 1.0f);   // +1 = self-loop
}

// fill + fused norm computation
__global__ void k_fill(const int* __restrict__ ei, const float* __restrict__ ea) {
    int e = blockIdx.x * blockDim.x + threadIdx.x;
    if (e >= Ee) return;
    int s = ei[e], d = ei[Ee + e];
    int pos = g_rowptr[d] + atomicAdd(&g_cur[d], 1);
    g_csrsrc[pos] = s;
    g_csrnorm[pos] = g_dinv[s] * ea[2 * e + 1] * g_dinv[d];
}

// ---------------- generic MMA GEMM (precompute only) ------------------------
__global__ __launch_bounds__(256) void k_mma_g(const float* __restrict__ A, int lda,
                                               int nch, int M,
                                               const unsigned* __restrict__ Bpk,
                                               float* __restrict__ out) {
    int tid = threadIdx.x, lane = tid & 31, w = tid >> 5;
    int qr = lane >> 2, qc = lane & 3;
    int r0 = blockIdx.x * 128 + w * 16 + qr, r1 = r0 + 8;
    bool v0 = r0 < M, v1 = r1 < M;
    float C[8][4] = {};
    for (int c = 0; c < nch; c++) {
        unsigned a[4][4];
        load_A_chunk(a, A, lda, r0, r1, v0, v1, c * 32, qc);
        mma_gate(C, a, Bpk + (size_t)c * 2048, lane);
    }
#pragma unroll
    for (int f = 0; f < 8; f++) {
        int col = 8 * f + 2 * qc;
        if (v0) *(float2*)(out + (size_t)r0 * 64 + col) = make_float2(C[f][0], C[f][1]);
        if (v1) *(float2*)(out + (size_t)r1 * 64 + col) = make_float2(C[f][2], C[f][3]);
    }
}

// ---------------- pre0 (128-row, 3 gates share A) ---------------------------
__global__ __launch_bounds__(256) void k_pre0m(const float* __restrict__ bu,
                                               const float* __restrict__ br,
                                               const float* __restrict__ bc) {
    int tid = threadIdx.x, lane = tid & 31, w = tid >> 5;
    int qr = lane >> 2, qc = lane & 3;
    int r0 = blockIdx.x * 128 + w * 16 + qr, r1 = r0 + 8;   // TN % 128 == 0
    float C[3][8][4] = {};
    for (int ch = 0; ch < 3; ch++) {
        const float* S = ch ? g_g0all : g_xt;
        int lda = ch ? 64 : 32;
        int k0 = (ch == 2) ? 32 : 0;
        unsigned a[4][4];
        load_A_chunk(a, S, lda, r0, r1, true, true, k0, qc);
#pragma unroll
        for (int g = 0; g < 3; g++)
            mma_gate(C[g], a, g_pkall + (size_t)(PK_PRE0 + g * 3 + ch) * 2048, lane);
    }
#pragma unroll
    for (int g = 0; g < 3; g++) {
        const float* b = (g == 0) ? bu : (g == 1) ? br : bc;
#pragma unroll
        for (int f = 0; f < 8; f++) {
            int col = 8 * f + 2 * qc;
            float2 b2 = *(const float2*)(b + col);
            *(float2*)(g_p0all + (size_t)r0 * 192 + g * 64 + col) =
                make_float2(C[g][f][0] + b2.x, C[g][f][1] + b2.y);
            *(float2*)(g_p0all + (size_t)r1 * 192 + g * 64 + col) =
                make_float2(C[g][f][2] + b2.x, C[g][f][3] + b2.y);
        }
    }
}

// ---------------- qkv (128-row, PDL) -----------------------------------------
__global__ __launch_bounds__(256) void k_qkvm(const float* __restrict__ ipb) {
    PDL_SYNC();
    int tid = threadIdx.x, lane = tid & 31, w = tid >> 5;
    int qr = lane >> 2, qc = lane & 3;
    int r0 = blockIdx.x * 128 + w * 16 + qr, r1 = r0 + 8;
    float C[3][8][4] = {};
    for (int ch = 0; ch < 2; ch++) {
        unsigned a[4][4];
        load_A_chunk(a, g_hseq, 64, r0, r1, true, true, ch * 32, qc);
#pragma unroll
        for (int g = 0; g < 3; g++)
            mma_gate(C[g], a, g_pkall + (size_t)(PK_QKV + g * 2 + ch) * 2048, lane);
    }
#pragma unroll
    for (int g = 0; g < 3; g++) {
#pragma unroll
        for (int f = 0; f < 8; f++) {
            int col = 8 * f + 2 * qc;
            float2 b2 = *(const float2*)(ipb + g * 64 + col);
            *(float2*)(g_qkv + (size_t)r0 * 192 + g * 64 + col) =
                make_float2(C[g][f][0] + b2.x, C[g][f][1] + b2.y);
            *(float2*)(g_qkv + (size_t)r1 * 192 + g * 64 + col) =
                make_float2(C[g][f][2] + b2.x, C[g][f][3] + b2.y);
        }
    }
    PDL_TRIGGER();
}

// ---------------- layer0 GCN agg over all t (fp32) ---------------------------
__global__ void k_agg_all(const float* __restrict__ bg) {
    int gw = blockIdx.x * (blockDim.x >> 5) + (threadIdx.x >> 5);
    if (gw >= TN) return;
    int t = gw / Nn, n = gw - t * Nn;
    int lane = threadIdx.x & 31;
    const float* xw = g_xw0all + (size_t)t * Nn * Hh;
    int beg = g_rowptr[n], end = g_rowptr[n + 1];
    float a0 = 0.f, a1 = 0.f;
#pragma unroll 4
    for (int p = beg; p < end; p++) {
        int s = g_csrsrc[p];
        float nm = g_csrnorm[p];
        a0 += nm * xw[(size_t)s * Hh + lane];
        a1 += nm * xw[(size_t)s * Hh + lane + 32];
    }
    float dv = g_dinv[n];
    float dd = dv * dv;
    a0 += dd * xw[(size_t)n * Hh + lane] + bg[lane];
    a1 += dd * xw[(size_t)n * Hh + lane + 32] + bg[lane + 32];
    g_g0all[(size_t)gw * Hh + lane] = sigmoidf_(a0);
    g_g0all[(size_t)gw * Hh + lane + 32] = sigmoidf_(a1);
}

// ---------------- per-step GCN agg (layer1, 1 warp/node, 0 smem, PDL) --------
__global__ void k_gcn_agg(const float* __restrict__ bg) {
    PDL_SYNC();
    int n = blockIdx.x * (blockDim.x >> 5) + (threadIdx.x >> 5);
    if (n < Nn) {
        int lane = threadIdx.x & 31;
        int beg = g_rowptr[n], end = g_rowptr[n + 1];
        float a0 = 0.f, a1 = 0.f;
#pragma unroll 4
        for (int p = beg; p < end; p++) {
            int s = g_csrsrc[p];
            float nm = g_csrnorm[p];
            a0 += nm * g_xw[(size_t)s * Hh + lane];
            a1 += nm * g_xw[(size_t)s * Hh + lane + 32];
        }
        float dv = g_dinv[n];
        float dd = dv * dv;
        a0 += dd * g_xw[(size_t)n * Hh + lane] + bg[lane];
        a1 += dd * g_xw[(size_t)n * Hh + lane + 32] + bg[lane + 32];
        g_gg[(size_t)n * Hh + lane] = sigmoidf_(a0);
        g_gg[(size_t)n * Hh + lane + 32] = sigmoidf_(a1);
    }
    PDL_TRIGGER();
}

// ---------------- layer0 urc + GRU update + xw=h@Wg1 (pipelined, PDL) --------
__global__ __launch_bounds__(128, 3) void k_urc0x(const float* __restrict__ p0,
                                                  float* __restrict__ h,
                                                  float* __restrict__ xw) {
    __shared__ unsigned U[64 * 72];
    PDL_SYNC();
    int tid = threadIdx.x, lane = tid & 31, w = tid >> 5;
    int qr = lane >> 2, qc = lane & 3;
    int rl0 = w * 16 + qr;
    int r0 = blockIdx.x * 64 + rl0, r1 = r0 + 8;
    bool v0 = r0 < Nn, v1 = r1 < Nn;
    float araw[16];
    load_A_raw(araw, h, 64, r0, r1, v0, v1, 0, qc);
    float Cu[8][4], Cr[8][4], Cc[8][4];
#pragma unroll
    for (int f = 0; f < 8; f++) {
        int col = 8 * f + 2 * qc;
        float2 z = make_float2(0.f, 0.f);
        float2 u0 = z, u1 = z, rr0 = z, rr1 = z, c0 = z, c1 = z;
        if (v0) {
            u0  = *(const float2*)(p0 + (size_t)r0 * 192 + col);
            rr0 = *(const float2*)(p0 + (size_t)r0 * 192 + 64 + col);
            c0  = *(const float2*)(p0 + (size_t)r0 * 192 + 128 + col);
        }
        if (v1) {
            u1  = *(const float2*)(p0 + (size_t)r1 * 192 + col);
            rr1 = *(const float2*)(p0 + (size_t)r1 * 192 + 64 + col);
            c1  = *(const float2*)(p0 + (size_t)r1 * 192 + 128 + col);
        }
        Cu[f][0] = u0.x;  Cu[f][1] = u0.y;  Cu[f][2] = u1.x;  Cu[f][3] = u1.y;
        Cr[f][0] = rr0.x; Cr[f][1] = rr0.y; Cr[f][2] = rr1.x; Cr[f][3] = rr1.y;
        Cc[f][0] = c0.x;  Cc[f][1] = c0.y;  Cc[f][2] = c1.x;  Cc[f][3] = c1.y;
    }
#pragma unroll
    for (int ch = 0; ch < 2; ch++) {
        unsigned a[4][4];
        cvt_frag(a, araw);
        if (ch == 0) load_A_raw(araw, h, 64, r0, r1, v0, v1, 32, qc);
        mma_gate(Cu, a, g_pkall + (size_t)(PK_URC0 + 0 + ch) * 2048, lane);
        mma_gate(Cr, a, g_pkall + (size_t)(PK_URC0 + 2 + ch) * 2048, lane);
    }
#pragma unroll
    for (int f = 0; f < 8; f++) {
        int col = 8 * f + 2 * qc;
#pragma unroll
        for (int half = 0; half < 2; half++) {
            int rl = rl0 + 8 * half;
            int row = blockIdx.x * 64 + rl;
            float u0 = sigmoidf_(Cu[f][2 * half + 0]);
            float u1 = sigmoidf_(Cu[f][2 * half + 1]);
            float rg0 = sigmoidf_(Cr[f][2 * half + 0]);
            float rg1 = sigmoidf_(Cr[f][2 * half + 1]);
            Cu[f][2 * half + 0] = u0;
            Cu[f][2 * half + 1] = u1;
            float2 hv = make_float2(0.f, 0.f);
            if (row < Nn) hv = *(const float2*)(h + (size_t)row * 64 + col);
            Cr[f][2 * half + 0] = hv.x;
            Cr[f][2 * half + 1] = hv.y;
            U[col * 72 + rl] = f2tf32(rg0 * hv.x);
            U[(col + 1) * 72 + rl] = f2tf32(rg1 * hv.y);
        }
    }
    __syncwarp();
    for (int ch = 0; ch < 2; ch++) {
        unsigned a[4][4];
        load_A_smemU(a, U, rl0, ch * 32, qc);
        mma_gate(Cc, a, g_pkall + (size_t)(PK_URC0 + 4 + ch) * 2048, lane);
    }
#pragma unroll
    for (int f = 0; f < 8; f++) {
        int col = 8 * f + 2 * qc;
#pragma unroll
        for (int half = 0; half < 2; half++) {
            int rl = rl0 + 8 * half;
            int row = blockIdx.x * 64 + rl;
            float hv0 = Cr[f][2 * half + 0], hv1 = Cr[f][2 * half + 1];
            float c0 = tanhf(Cc[f][2 * half + 0]);
            float c1 = tanhf(Cc[f][2 * half + 1]);
            float u0 = Cu[f][2 * half + 0], u1 = Cu[f][2 * half + 1];
            float o0 = u0 * hv0 + (1.f - u0) * c0;
            float o1 = u1 * hv1 + (1.f - u1) * c1;
            if (row < Nn) *(float2*)(h + (size_t)row * 64 + col) = make_float2(o0, o1);
            U[col * 72 + rl] = f2tf32(o0);
            U[(col + 1) * 72 + rl] = f2tf32(o1);
        }
    }
    __syncwarp();
    float Cx[8][4] = {};
    for (int ch = 0; ch < 2; ch++) {
        unsigned a[4][4];
        load_A_smemU(a, U, rl0, ch * 32, qc);
        mma_gate(Cx, a, g_pkall + (size_t)(PK_WG1 + ch) * 2048, lane);
    }
#pragma unroll
    for (int f = 0; f < 8; f++) {
        int col = 8 * f + 2 * qc;
        if (v0) *(float2*)(xw + (size_t)r0 * 64 + col) = make_float2(Cx[f][0], Cx[f][1]);
        if (v1) *(float2*)(xw + (size_t)r1 * 64 + col) = make_float2(Cx[f][2], Cx[f][3]);
    }
    PDL_TRIGGER();
}

// ---------------- layer1 urc + GRU update (pipelined K=192, PDL) -------------
__global__ __launch_bounds__(128, 3) void k_urc1m(
    const float* __restrict__ h0,
    const float* __restrict__ bu, const float* __restrict__ br,
    const float* __restrict__ bc,
    float* __restrict__ h, float* __restrict__ hseq) {
    __shared__ unsigned U[64 * 72];
    PDL_SYNC();
    int tid = threadIdx.x, lane = tid & 31, w = tid >> 5;
    int qr = lane >> 2, qc = lane & 3;
    int rl0 = w * 16 + qr;
    int r0 = blockIdx.x * 64 + rl0, r1 = r0 + 8;
    bool v0 = r0 < Nn, v1 = r1 < Nn;
    float Cu[8][4] = {}, Cr[8][4] = {}, Cc[8][4] = {};
    float araw[16];
    load_A_raw(araw, h0, 64, r0, r1, v0, v1, 0, qc);
#pragma unroll
    for (int ch = 0; ch < 6; ch++) {
        unsigned a[4][4];
        cvt_frag(a, araw);
        if (ch < 5) {
            int cn = ch + 1;
            const float* Sn = (cn < 2) ? h0 : (cn < 4) ? g_gg : h;
            load_A_raw(araw, Sn, 64, r0, r1, v0, v1, (cn & 1) * 32, qc);
        }
        mma_gate(Cu, a, g_pkall + (size_t)(PK_URC1 + ch) * 2048, lane);
        mma_gate(Cr, a, g_pkall + (size_t)(PK_URC1 + 6 + ch) * 2048, lane);
        if (ch < 4) mma_gate(Cc, a, g_pkall + (size_t)(PK_URC1 + 12 + ch) * 2048, lane);
    }
#pragma unroll
    for (int f = 0; f < 8; f++) {
        int col = 8 * f + 2 * qc;
        float2 bu2 = *(const float2*)(bu + col);
        float2 br2 = *(const float2*)(br + col);
#pragma unroll
        for (int half = 0; half < 2; half++) {
            int rl = rl0 + 8 * half;
            int row = blockIdx.x * 64 + rl;
            float u0 = sigmoidf_(Cu[f][2 * half + 0] + bu2.x);
            float u1 = sigmoidf_(Cu[f][2 * half + 1] + bu2.y);
            float rg0 = sigmoidf_(Cr[f][2 * half + 0] + br2.x);
            float rg1 = sigmoidf_(Cr[f][2 * half + 1] + br2.y);
            Cu[f][2 * half + 0] = u0;
            Cu[f][2 * half + 1] = u1;
            float2 hv = make_float2(0.f, 0.f);
            if (row < Nn) hv = *(const float2*)(h + (size_t)row * 64 + col);
            Cr[f][2 * half + 0] = hv.x;
            Cr[f][2 * half + 1] = hv.y;
            U[col * 72 + rl] = f2tf32(rg0 * hv.x);
            U[(col + 1) * 72 + rl] = f2tf32(rg1 * hv.y);
        }
    }
    __syncwarp();
    for (int ch = 0; ch < 2; ch++) {
        unsigned a[4][4];
        load_A_smemU(a, U, rl0, ch * 32, qc);
        mma_gate(Cc, a, g_pkall + (size_t)(PK_URC1 + 16 + ch) * 2048, lane);
    }
#pragma unroll
    for (int f = 0; f < 8; f++) {
        int col = 8 * f + 2 * qc;
        float2 bc2 = *(const float2*)(bc + col);
#pragma unroll
        for (int half = 0; half < 2; half++) {
            int row = blockIdx.x * 64 + rl0 + 8 * half;
            if (row >= Nn) continue;
            float hv0 = Cr[f][2 * half + 0], hv1 = Cr[f][2 * half + 1];
            float c0 = tanhf(Cc[f][2 * half + 0] + bc2.x);
            float c1 = tanhf(Cc[f][2 * half + 1] + bc2.y);
            float u0 = Cu[f][2 * half + 0], u1 = Cu[f][2 * half + 1];
            float2 o = make_float2(u0 * hv0 + (1.f - u0) * c0,
                                   u1 * hv1 + (1.f - u1) * c1);
            *(float2*)(h + (size_t)row * 64 + col) = o;
            *(float2*)(hseq + (size_t)row * 64 + col) = o;
        }
    }
    PDL_TRIGGER();
}

// ---------------- attention tail (PDL) ---------------------------------------
__global__ __launch_bounds__(128) void k_attn2(
    const float* __restrict__ opb,
    const float* __restrict__ ow, const float* __restrict__ ob,
    float* __restrict__ out) {
    __shared__ float s_qkv[4][Tt * 192];
    __shared__ float s_sc[4][2 * Tt * Tt];
    __shared__ float s_cs[4][2 * Tt];
    __shared__ float s_ob[4][Hh];
    __shared__ float s_ha[4][Hh];
    PDL_SYNC();
    int w = threadIdx.x >> 5, lane = threadIdx.x & 31;
    int n = blockIdx.x * 4 + w;
    if (n >= Nn) return;
    float* qkv = s_qkv[w];
    float* sc = s_sc[w];
    float* cs = s_cs[w];
    float* obw = s_ob[w];
    float* haw = s_ha[w];

    for (int i = lane; i < Tt * 48; i += 32) {
        int t = i / 48, r = i % 48;
        *(float4*)&qkv[t * 192 + r * 4] =
            *(const float4*)&g_qkv[((size_t)t * Nn + n) * 192 + r * 4];
    }
    __syncwarp();
    for (int idx = lane; idx < 2 * Tt * Tt; idx += 32) {
        int hd = idx / (Tt * Tt);
        int r = idx % (Tt * Tt);
        int t = r / Tt, s = r % Tt;
        const float* qp = &qkv[t * 192 + hd * 32];
        const float* kp = &qkv[s * 192 + 64 + hd * 32];
        float a = 0.f;
#pragma unroll
        for (int d = 0; d < 32; d++) a += qp[d] * kp[d];
        sc[idx] = a * 0.17677669529663687f;
    }
    __syncwarp();
    if (lane < 2 * Tt) {
        float* row = &sc[lane * Tt];
        float mx = row[0];
#pragma unroll
        for (int s = 1; s < Tt; s++) mx = fmaxf(mx, row[s]);
        float sum = 0.f;
#pragma unroll
        for (int s = 0; s < Tt; s++) { float e = __expf(row[s] - mx); row[s] = e; sum += e; }
        float inv = 1.0f / sum;
#pragma unroll
        for (int s = 0; s < Tt; s++) row[s] *= inv;
    }
    __syncwarp();
    if (lane < 2 * Tt) {
        int hd = lane / Tt, s = lane % Tt;
        float a = 0.f;
#pragma unroll
        for (int t = 0; t < Tt; t++) a += sc[hd * Tt * Tt + t * Tt + s];
        cs[lane] = a * (1.0f / 12.0f);
    }
    __syncwarp();
    for (int m = 0; m < 2; m++) {
        int j = lane + 32 * m;
        int hd = j >> 5;
        float a = 0.f;
#pragma unroll
        for (int s = 0; s < Tt; s++) a += cs[hd * Tt + s] * qkv[s * 192 + 128 + j];
        obw[j] = a;
    }
    __syncwarp();
    for (int m = 0; m < 2; m++) {
        int i = lane + 32 * m;
        float a = opb[i];
#pragma unroll
        for (int j = 0; j < Hh; j++) a += g_opwT[j * Hh + i] * obw[j];
        haw[i] = a;
    }
    __syncwarp();
    if (lane < OUTD) {
        float a = ob[lane];
#pragma unroll
        for (int i = 0; i < Hh; i++) a += haw[i] * ow[(size_t)i * OUTD + lane];
        out[(size_t)n * OUTD + lane] = a;
    }
}

// ---------------- host ----------------
static cudaLaunchConfig_t pdl_cfg(dim3 grid, dim3 block, cudaLaunchAttribute* attr) {
    cudaLaunchConfig_t cfg = {};
    cfg.gridDim = grid;
    cfg.blockDim = block;
    cfg.dynamicSmemBytes = 0;
    cfg.stream = 0;
    attr[0].id = cudaLaunchAttributeProgrammaticStreamSerialization;
    attr[0].val.programmaticStreamSerializationAllowed = 1;
    cfg.attrs = attr;
    cfg.numAttrs = 1;
    return cfg;
}

extern "C" void kernel_launch(void* const* d_in, const int* in_sizes, int n_in,
                              void* d_out, int out_size) {
    (void)in_sizes; (void)n_in; (void)out_size;
    const float* x   = (const float*)d_in[0];
    const int*   ei  = (const int*)d_in[1];
    const float* ea  = (const float*)d_in[2];
    const float* Wg0 = (const float*)d_in[3];
    const float* bg0 = (const float*)d_in[4];
    const float* Wu0 = (const float*)d_in[5];
    const float* bu0 = (const float*)d_in[6];
    const float* Wr0 = (const float*)d_in[7];
    const float* br0 = (const float*)d_in[8];
    const float* Wc0 = (const float*)d_in[9];
    const float* bc0 = (const float*)d_in[10];
    const float* Wg1 = (const float*)d_in[11];
    const float* bg1 = (const float*)d_in[12];
    const float* Wu1 = (const float*)d_in[13];
    const float* bu1 = (const float*)d_in[14];
    const float* Wr1 = (const float*)d_in[15];
    const float* br1 = (const float*)d_in[16];
    const float* Wc1 = (const float*)d_in[17];
    const float* bc1 = (const float*)d_in[18];
    const float* ipw = (const float*)d_in[19];
    const float* ipb = (const float*)d_in[20];
    const float* opw = (const float*)d_in[21];
    const float* opb = (const float*)d_in[22];
    const float* ow  = (const float*)d_in[23];
    const float* ob  = (const float*)d_in[24];
    float* out = (float*)d_out;

    void *p_deg, *p_cnt, *p_cur, *p_h0, *p_h1, *p_xt, *p_hseq;
    void *p_xw0all, *p_p0all, *p_xw, *p_ipwT, *p_pkall;
    cudaGetSymbolAddress(&p_deg, g_deg);
    cudaGetSymbolAddress(&p_cnt, g_cnt);
    cudaGetSymbolAddress(&p_cur, g_cur);
    cudaGetSymbolAddress(&p_h0, g_h0);
    cudaGetSymbolAddress(&p_h1, g_h1);
    cudaGetSymbolAddress(&p_xt, g_xt);
    cudaGetSymbolAddress(&p_hseq, g_hseq);
    cudaGetSymbolAddress(&p_xw0all, g_xw0all);
    cudaGetSymbolAddress(&p_p0all, g_p0all);
    cudaGetSymbolAddress(&p_xw, g_xw);
    cudaGetSymbolAddress(&p_ipwT, g_ipwT);
    cudaGetSymbolAddress(&p_pkall, g_pkall);

    cudaMemsetAsync(p_deg, 0, Nn * sizeof(float), 0);
    cudaMemsetAsync(p_cnt, 0, Nn * sizeof(int), 0);
    cudaMemsetAsync(p_cur, 0, Nn * sizeof(int), 0);
    cudaMemsetAsync(p_h0, 0, (size_t)Nn * Hh * sizeof(float), 0);
    cudaMemsetAsync(p_h1, 0, (size_t)Nn * Hh * sizeof(float), 0);

    k_transpose<<<(Nn * Ff * Tt + 255) / 256, 256>>>(x);
    k_trW<<<(192 * Hh + 255) / 256, 256>>>(ipw, opw);
    k_deg_hist<<<(Ee + 255) / 256, 256>>>(ei, ea);
    k_scan<<<1, 1024>>>();                       // scan + dinv
    k_fill<<<(Ee + 255) / 256, 256>>>(ei, ea);   // fill + norm

    // ---- single-launch weight packing ----
    float* ipwT = (float*)p_ipwT;
    PackTab tab;
    int gi = 0;
    tab.src[gi] = Wg0; tab.ldw[gi++] = 64;
    const float* Ws0[3] = {Wu0, Wr0, Wc0};
    for (int g = 0; g < 3; g++)
        for (int c = 0; c < 3; c++) { tab.src[gi] = Ws0[g] + (size_t)c * 32 * 64; tab.ldw[gi++] = 64; }
    for (int g = 0; g < 3; g++)
        for (int c = 0; c < 2; c++) { tab.src[gi] = Ws0[g] + (size_t)(96 + c * 32) * 64; tab.ldw[gi++] = 64; }
    for (int c = 0; c < 2; c++) { tab.src[gi] = Wg1 + (size_t)c * 32 * 64; tab.ldw[gi++] = 64; }
    const float* Ws1[3] = {Wu1, Wr1, Wc1};
    for (int g = 0; g < 3; g++)
        for (int c = 0; c < 6; c++) { tab.src[gi] = Ws1[g] + (size_t)c * 32 * 64; tab.ldw[gi++] = 64; }
    for (int g = 0; g < 3; g++)
        for (int c = 0; c < 2; c++) { tab.src[gi] = ipwT + g * 64 + (size_t)c * 32 * 192; tab.ldw[gi++] = 192; }
    k_packall<<<(42 * 512 + 255) / 256, 256>>>(tab);

    // ---- hoisted precomputes ----
    k_mma_g<<<TN / 128, 256>>>((const float*)p_xt, Ff, 1, TN,
                               (const unsigned*)p_pkall + (size_t)PK_WG0 * 2048, (float*)p_xw0all);
    k_agg_all<<<(TN + 7) / 8, 256>>>(bg0);
    k_pre0m<<<TN / 128, 256>>>(bu0, br0, bc0);

    const int AGG_GRID = (Nn + 7) / 8;
    float* h0 = (float*)p_h0;
    float* h1 = (float*)p_h1;
    float* xw = (float*)p_xw;
    const float* p0all = (const float*)p_p0all;

    cudaLaunchAttribute at0[1], at1[1], at2[1];
    for (int t = 0; t < Tt; t++) {
        const float* p0t = p0all + (size_t)t * Nn * 192;
        float* hseqt = (float*)p_hseq + (size_t)t * Nn * Hh;
        {
            cudaLaunchConfig_t cfg = pdl_cfg(dim3(GB), dim3(128), at0);
            cudaLaunchKernelEx(&cfg, k_urc0x, p0t, h0, xw);
        }
        {
            cudaLaunchConfig_t cfg = pdl_cfg(dim3(AGG_GRID), dim3(256), at1);
            cudaLaunchKernelEx(&cfg, k_gcn_agg, bg1);
        }
        {
            cudaLaunchConfig_t cfg = pdl_cfg(dim3(GB), dim3(128), at2);
            cudaLaunchKernelEx(&cfg, k_urc1m, (const float*)h0, bu1, br1, bc1, h1, hseqt);
        }
    }

    {
        cudaLaunchAttribute atq[1];
        cudaLaunchConfig_t cfg = pdl_cfg(dim3(TN / 128), dim3(256), atq);
        cudaLaunchKernelEx(&cfg, k_qkvm, ipb);
    }
    {
        cudaLaunchAttribute ata[1];
        cudaLaunchConfig_t cfg = pdl_cfg(dim3((Nn + 3) / 4), dim3(128), ata);
        cudaLaunchKernelEx(&cfg, k_attn2, opb, ow, ob, out);
    }
}

// round 14
// speedup vs baseline: 1.0204x; 1.0204x over previous
#include <cuda_runtime.h>
#include <math.h>
#include <stdint.h>

#define Nn 20000
#define Ff 32
#define Tt 12
#define Hh 64
#define Ee 320000
#define OUTD 12
#define TN (Tt * Nn)
#define GB 313

// ---------------- scratch ----------------
static __device__ float g_xt[(size_t)TN * Ff];
static __device__ float g_deg[Nn];
static __device__ float g_dinv[Nn];
static __device__ int   g_cnt[Nn];
static __device__ int   g_cur[Nn];
static __device__ int   g_rowptr[Nn + 1];
static __device__ int   g_csrsrc[Ee];
static __device__ float g_csrnorm[Ee];
static __device__ float g_xw0all[(size_t)TN * Hh];
static __device__ float g_g0all[(size_t)TN * Hh];
static __device__ float g_p0all[(size_t)TN * 192];
static __device__ float g_xw[(size_t)Nn * Hh];
static __device__ float g_gg[(size_t)Nn * Hh];
static __device__ float g_h0[(size_t)Nn * Hh];
static __device__ float g_h1[(size_t)Nn * Hh];
static __device__ float g_hseq[(size_t)TN * Hh];
static __device__ float g_qkv[(size_t)TN * 192];
static __device__ float g_ipwT[Hh * 192];
static __device__ float g_opwT[Hh * Hh];

// unified pre-packed tf32 b-fragments: 42 chunks x 2048 unsigned
static __device__ unsigned g_pkall[42 * 2048];
#define PK_WG0  0
#define PK_PRE0 1
#define PK_URC0 10
#define PK_WG1  16
#define PK_URC1 18
#define PK_QKV  36

struct PackTab { const float* src[42]; int ldw[42]; };

__device__ __forceinline__ float sigmoidf_(float x) { return 1.0f / (1.0f + __expf(-x)); }

__device__ __forceinline__ unsigned f2tf32(float f) {
    unsigned r;
    asm("cvt.rna.tf32.f32 %0, %1;" : "=r"(r) : "f"(f));
    return r;
}

__device__ __forceinline__ void mma_tf32(float c[4], const unsigned a[4], unsigned b0, unsigned b1) {
    asm volatile(
        "mma.sync.aligned.m16n8k8.row.col.f32.tf32.tf32.f32 "
        "{%0,%1,%2,%3}, {%4,%5,%6,%7}, {%8,%9}, {%0,%1,%2,%3};"
        : "+f"(c[0]), "+f"(c[1]), "+f"(c[2]), "+f"(c[3])
        : "r"(a[0]), "r"(a[1]), "r"(a[2]), "r"(a[3]), "r"(b0), "r"(b1));
}

__device__ __forceinline__ void load_A_raw(float x[16], const float* __restrict__ A,
                                           int lda, int r0, int r1, bool v0, bool v1,
                                           int k0, int qc) {
#pragma unroll
    for (int s = 0; s < 4; s++) {
        int k = k0 + 8 * s + qc;
        x[4 * s + 0] = v0 ? A[(size_t)r0 * lda + k] : 0.f;
        x[4 * s + 1] = v1 ? A[(size_t)r1 * lda + k] : 0.f;
        x[4 * s + 2] = v0 ? A[(size_t)r0 * lda + k + 4] : 0.f;
        x[4 * s + 3] = v1 ? A[(size_t)r1 * lda + k + 4] : 0.f;
    }
}

__device__ __forceinline__ void cvt_frag(unsigned a[4][4], const float x[16]) {
#pragma unroll
    for (int s = 0; s < 4; s++)
#pragma unroll
        for (int j = 0; j < 4; j++) a[s][j] = f2tf32(x[4 * s + j]);
}

__device__ __forceinline__ void load_A_chunk(unsigned a[4][4], const float* __restrict__ A,
                                             int lda, int r0, int r1, bool v0, bool v1,
                                             int k0, int qc) {
    float x[16];
    load_A_raw(x, A, lda, r0, r1, v0, v1, k0, qc);
    cvt_frag(a, x);
}

__device__ __forceinline__ void load_A_smemU(unsigned a[4][4], const unsigned* U,
                                             int rl0, int k0, int qc) {
#pragma unroll
    for (int s = 0; s < 4; s++) {
        int k = k0 + 8 * s + qc;
        a[s][0] = U[k * 72 + rl0];
        a[s][1] = U[k * 72 + rl0 + 8];
        a[s][2] = U[(k + 4) * 72 + rl0];
        a[s][3] = U[(k + 4) * 72 + rl0 + 8];
    }
}

__device__ __forceinline__ void mma_gate(float C[8][4], const unsigned a[4][4],
                                         const unsigned* __restrict__ Bpk, int lane) {
    const uint4* B4 = (const uint4*)Bpk;
#pragma unroll
    for (int s = 0; s < 4; s++)
#pragma unroll
        for (int f2 = 0; f2 < 4; f2++) {
            uint4 b = B4[(s * 4 + f2) * 32 + lane];
            mma_tf32(C[2 * f2], a[s], b.x, b.y);
            mma_tf32(C[2 * f2 + 1], a[s], b.z, b.w);
        }
}

// ---------------- single-launch weight pack ----------------------------------
__global__ void k_packall(PackTab tab) {
    int tid = blockIdx.x * blockDim.x + threadIdx.x;
    if (tid >= 42 * 512) return;
    int g = tid >> 9, r = tid & 511;
    const float* W = tab.src[g];
    int ldw = tab.ldw[g];
    int s = r >> 7, f2 = (r >> 5) & 3, lane = r & 31;
    int qr = lane >> 2, qc = lane & 3;
    int k1 = 8 * s + qc, k2 = k1 + 4;
    int n1 = 16 * f2 + qr, n2 = n1 + 8;
    uint4 o;
    o.x = f2tf32(W[(size_t)k1 * ldw + n1]);
    o.y = f2tf32(W[(size_t)k2 * ldw + n1]);
    o.z = f2tf32(W[(size_t)k1 * ldw + n2]);
    o.w = f2tf32(W[(size_t)k2 * ldw + n2]);
    ((uint4*)g_pkall)[tid] = o;
}

// ---------------- merged elementwise preproc ---------------------------------
// blocks [0, TB0): transpose ; [TB0, TB0+48): trW ; [TB0+48, TB0+48+1250): deg_hist
#define TB0 ((Nn * Ff * Tt + 255) / 256)
#define TB1 48
#define TB2 ((Ee + 255) / 256)
__global__ void k_prep(const float* __restrict__ x,
                       const float* __restrict__ ipw, const float* __restrict__ opw,
                       const int* __restrict__ ei, const float* __restrict__ ea) {
    int b = blockIdx.x;
    if (b < TB0) {
        int idx = b * 256 + threadIdx.x;
        if (idx >= Nn * Ff * Tt) return;
        int f = idx & (Ff - 1);
        int t = (idx / Ff) % Tt;
        int n = idx / (Ff * Tt);
        g_xt[(size_t)t * Nn * Ff + (size_t)n * Ff + f] =
            x[(size_t)n * Ff * Tt + (size_t)f * Tt + t];
    } else if (b < TB0 + TB1) {
        int i = (b - TB0) * 256 + threadIdx.x;
        if (i < 192 * Hh) { int r = i / Hh, c = i % Hh; g_ipwT[c * 192 + r] = ipw[i]; }
        if (i < Hh * Hh)  { int r = i / Hh, c = i % Hh; g_opwT[c * Hh + r] = opw[i]; }
    } else {
        int e = (b - TB0 - TB1) * 256 + threadIdx.x;
        if (e >= Ee) return;
        int d = ei[Ee + e];
        atomicAdd(&g_deg[d], ea[2 * e + 1]);
        atomicAdd(&g_cnt[d], 1);
    }
}

// ---------------- fast scan (shuffle-based) + fused dinv ----------------------
__global__ __launch_bounds__(1024) void k_scan() {
    const int ELT = 20;                    // 1024*20 = 20480 >= Nn
    int tid = threadIdx.x;
    int base = tid * ELT;
    int v[ELT];
    int sum = 0;
#pragma unroll
    for (int i = 0; i < ELT; i++) {
        int idx = base + i;
        v[i] = (idx < Nn) ? g_cnt[idx] : 0;
        sum += v[i];
    }
    int lane = tid & 31, wid = tid >> 5;
    // warp inclusive scan of per-thread sums
    int s = sum;
#pragma unroll
    for (int off = 1; off < 32; off <<= 1) {
        int t2 = __shfl_up_sync(0xffffffffu, s, off);
        if (lane >= off) s += t2;
    }
    __shared__ int wsum[32];
    if (lane == 31) wsum[wid] = s;
    __syncthreads();
    if (wid == 0) {
        int ws = wsum[lane];
#pragma unroll
        for (int off = 1; off < 32; off <<= 1) {
            int t2 = __shfl_up_sync(0xffffffffu, ws, off);
            if (lane >= off) ws += t2;
        }
        wsum[lane] = ws;
    }
    __syncthreads();
    int offset = ((wid > 0) ? wsum[wid - 1] : 0) + (s - sum);   // exclusive prefix
    if (tid == 0) g_rowptr[0] = 0;
    int run = offset;
#pragma unroll
    for (int i = 0; i < ELT; i++) {
        run += v[i];
        int idx = base + i;
        if (idx < Nn) g_rowptr[idx + 1] = run;
    }
    for (int n = tid; n < Nn; n += 1024)
        g_dinv[n] = rsqrtf(g_deg[n] + 1.0f);   // +1 = self-loop
}

// fill + fused norm computation
__global__ void k_fill(const int* __restrict__ ei, const float* __restrict__ ea) {
    int e = blockIdx.x * blockDim.x + threadIdx.x;
    if (e >= Ee) return;
    int s = ei[e], d = ei[Ee + e];
    int pos = g_rowptr[d] + atomicAdd(&g_cur[d], 1);
    g_csrsrc[pos] = s;
    g_csrnorm[pos] = g_dinv[s] * ea[2 * e + 1] * g_dinv[d];
}

// ---------------- generic MMA GEMM (precompute only) ------------------------
__global__ __launch_bounds__(256) void k_mma_g(const float* __restrict__ A, int lda,
                                               int nch, int M,
                                               const unsigned* __restrict__ Bpk,
                                               float* __restrict__ out) {
    int tid = threadIdx.x, lane = tid & 31, w = tid >> 5;
    int qr = lane >> 2, qc = lane & 3;
    int r0 = blockIdx.x * 128 + w * 16 + qr, r1 = r0 + 8;
    bool v0 = r0 < M, v1 = r1 < M;
    float C[8][4] = {};
    for (int c = 0; c < nch; c++) {
        unsigned a[4][4];
        load_A_chunk(a, A, lda, r0, r1, v0, v1, c * 32, qc);
        mma_gate(C, a, Bpk + (size_t)c * 2048, lane);
    }
#pragma unroll
    for (int f = 0; f < 8; f++) {
        int col = 8 * f + 2 * qc;
        if (v0) *(float2*)(out + (size_t)r0 * 64 + col) = make_float2(C[f][0], C[f][1]);
        if (v1) *(float2*)(out + (size_t)r1 * 64 + col) = make_float2(C[f][2], C[f][3]);
    }
}

// ---------------- pre0 (128-row, 3 gates share A) ---------------------------
__global__ __launch_bounds__(256) void k_pre0m(const float* __restrict__ bu,
                                               const float* __restrict__ br,
                                               const float* __restrict__ bc) {
    int tid = threadIdx.x, lane = tid & 31, w = tid >> 5;
    int qr = lane >> 2, qc = lane & 3;
    int r0 = blockIdx.x * 128 + w * 16 + qr, r1 = r0 + 8;   // TN % 128 == 0
    float C[3][8][4] = {};
    for (int ch = 0; ch < 3; ch++) {
        const float* S = ch ? g_g0all : g_xt;
        int lda = ch ? 64 : 32;
        int k0 = (ch == 2) ? 32 : 0;
        unsigned a[4][4];
        load_A_chunk(a, S, lda, r0, r1, true, true, k0, qc);
#pragma unroll
        for (int g = 0; g < 3; g++)
            mma_gate(C[g], a, g_pkall + (size_t)(PK_PRE0 + g * 3 + ch) * 2048, lane);
    }
#pragma unroll
    for (int g = 0; g < 3; g++) {
        const float* b = (g == 0) ? bu : (g == 1) ? br : bc;
#pragma unroll
        for (int f = 0; f < 8; f++) {
            int col = 8 * f + 2 * qc;
            float2 b2 = *(const float2*)(b + col);
            *(float2*)(g_p0all + (size_t)r0 * 192 + g * 64 + col) =
                make_float2(C[g][f][0] + b2.x, C[g][f][1] + b2.y);
            *(float2*)(g_p0all + (size_t)r1 * 192 + g * 64 + col) =
                make_float2(C[g][f][2] + b2.x, C[g][f][3] + b2.y);
        }
    }
}

// ---------------- qkv (128-row) ----------------------------------------------
__global__ __launch_bounds__(256) void k_qkvm(const float* __restrict__ ipb) {
    int tid = threadIdx.x, lane = tid & 31, w = tid >> 5;
    int qr = lane >> 2, qc = lane & 3;
    int r0 = blockIdx.x * 128 + w * 16 + qr, r1 = r0 + 8;
    float C[3][8][4] = {};
    for (int ch = 0; ch < 2; ch++) {
        unsigned a[4][4];
        load_A_chunk(a, g_hseq, 64, r0, r1, true, true, ch * 32, qc);
#pragma unroll
        for (int g = 0; g < 3; g++)
            mma_gate(C[g], a, g_pkall + (size_t)(PK_QKV + g * 2 + ch) * 2048, lane);
    }
#pragma unroll
    for (int g = 0; g < 3; g++) {
#pragma unroll
        for (int f = 0; f < 8; f++) {
            int col = 8 * f + 2 * qc;
            float2 b2 = *(const float2*)(ipb + g * 64 + col);
            *(float2*)(g_qkv + (size_t)r0 * 192 + g * 64 + col) =
                make_float2(C[g][f][0] + b2.x, C[g][f][1] + b2.y);
            *(float2*)(g_qkv + (size_t)r1 * 192 + g * 64 + col) =
                make_float2(C[g][f][2] + b2.x, C[g][f][3] + b2.y);
        }
    }
}

// ---------------- layer0 GCN agg over all t (fp32) ---------------------------
__global__ void k_agg_all(const float* __restrict__ bg) {
    int gw = blockIdx.x * (blockDim.x >> 5) + (threadIdx.x >> 5);
    if (gw >= TN) return;
    int t = gw / Nn, n = gw - t * Nn;
    int lane = threadIdx.x & 31;
    const float* xw = g_xw0all + (size_t)t * Nn * Hh;
    int beg = g_rowptr[n], end = g_rowptr[n + 1];
    float a0 = 0.f, a1 = 0.f;
#pragma unroll 4
    for (int p = beg; p < end; p++) {
        int s = g_csrsrc[p];
        float nm = g_csrnorm[p];
        a0 += nm * xw[(size_t)s * Hh + lane];
        a1 += nm * xw[(size_t)s * Hh + lane + 32];
    }
    float dv = g_dinv[n];
    float dd = dv * dv;
    a0 += dd * xw[(size_t)n * Hh + lane] + bg[lane];
    a1 += dd * xw[(size_t)n * Hh + lane + 32] + bg[lane + 32];
    g_g0all[(size_t)gw * Hh + lane] = sigmoidf_(a0);
    g_g0all[(size_t)gw * Hh + lane + 32] = sigmoidf_(a1);
}

// ---------------- per-step GCN agg (layer1, 1 warp/node, 0 smem) -------------
__global__ void k_gcn_agg(const float* __restrict__ bg) {
    int n = blockIdx.x * (blockDim.x >> 5) + (threadIdx.x >> 5);
    if (n >= Nn) return;
    int lane = threadIdx.x & 31;
    int beg = g_rowptr[n], end = g_rowptr[n + 1];
    float a0 = 0.f, a1 = 0.f;
#pragma unroll 4
    for (int p = beg; p < end; p++) {
        int s = g_csrsrc[p];
        float nm = g_csrnorm[p];
        a0 += nm * g_xw[(size_t)s * Hh + lane];
        a1 += nm * g_xw[(size_t)s * Hh + lane + 32];
    }
    float dv = g_dinv[n];
    float dd = dv * dv;
    a0 += dd * g_xw[(size_t)n * Hh + lane] + bg[lane];
    a1 += dd * g_xw[(size_t)n * Hh + lane + 32] + bg[lane + 32];
    g_gg[(size_t)n * Hh + lane] = sigmoidf_(a0);
    g_gg[(size_t)n * Hh + lane + 32] = sigmoidf_(a1);
}

// ---------------- layer0 urc + GRU update + xw=h@Wg1 (pipelined) -------------
__global__ __launch_bounds__(128, 3) void k_urc0x(const float* __restrict__ p0,
                                                  float* __restrict__ h,
                                                  float* __restrict__ xw) {
    __shared__ unsigned U[64 * 72];
    int tid = threadIdx.x, lane = tid & 31, w = tid >> 5;
    int qr = lane >> 2, qc = lane & 3;
    int rl0 = w * 16 + qr;
    int r0 = blockIdx.x * 64 + rl0, r1 = r0 + 8;
    bool v0 = r0 < Nn, v1 = r1 < Nn;
    float araw[16];
    load_A_raw(araw, h, 64, r0, r1, v0, v1, 0, qc);
    float Cu[8][4], Cr[8][4], Cc[8][4];
#pragma unroll
    for (int f = 0; f < 8; f++) {
        int col = 8 * f + 2 * qc;
        float2 z = make_float2(0.f, 0.f);
        float2 u0 = z, u1 = z, rr0 = z, rr1 = z, c0 = z, c1 = z;
        if (v0) {
            u0  = *(const float2*)(p0 + (size_t)r0 * 192 + col);
            rr0 = *(const float2*)(p0 + (size_t)r0 * 192 + 64 + col);
            c0  = *(const float2*)(p0 + (size_t)r0 * 192 + 128 + col);
        }
        if (v1) {
            u1  = *(const float2*)(p0 + (size_t)r1 * 192 + col);
            rr1 = *(const float2*)(p0 + (size_t)r1 * 192 + 64 + col);
            c1  = *(const float2*)(p0 + (size_t)r1 * 192 + 128 + col);
        }
        Cu[f][0] = u0.x;  Cu[f][1] = u0.y;  Cu[f][2] = u1.x;  Cu[f][3] = u1.y;
        Cr[f][0] = rr0.x; Cr[f][1] = rr0.y; Cr[f][2] = rr1.x; Cr[f][3] = rr1.y;
        Cc[f][0] = c0.x;  Cc[f][1] = c0.y;  Cc[f][2] = c1.x;  Cc[f][3] = c1.y;
    }
#pragma unroll
    for (int ch = 0; ch < 2; ch++) {
        unsigned a[4][4];
        cvt_frag(a, araw);
        if (ch == 0) load_A_raw(araw, h, 64, r0, r1, v0, v1, 32, qc);
        mma_gate(Cu, a, g_pkall + (size_t)(PK_URC0 + 0 + ch) * 2048, lane);
        mma_gate(Cr, a, g_pkall + (size_t)(PK_URC0 + 2 + ch) * 2048, lane);
    }
#pragma unroll
    for (int f = 0; f < 8; f++) {
        int col = 8 * f + 2 * qc;
#pragma unroll
        for (int half = 0; half < 2; half++) {
            int rl = rl0 + 8 * half;
            int row = blockIdx.x * 64 + rl;
            float u0 = sigmoidf_(Cu[f][2 * half + 0]);
            float u1 = sigmoidf_(Cu[f][2 * half + 1]);
            float rg0 = sigmoidf_(Cr[f][2 * half + 0]);
            float rg1 = sigmoidf_(Cr[f][2 * half + 1]);
            Cu[f][2 * half + 0] = u0;
            Cu[f][2 * half + 1] = u1;
            float2 hv = make_float2(0.f, 0.f);
            if (row < Nn) hv = *(const float2*)(h + (size_t)row * 64 + col);
            Cr[f][2 * half + 0] = hv.x;
            Cr[f][2 * half + 1] = hv.y;
            U[col * 72 + rl] = f2tf32(rg0 * hv.x);
            U[(col + 1) * 72 + rl] = f2tf32(rg1 * hv.y);
        }
    }
    __syncwarp();
    for (int ch = 0; ch < 2; ch++) {
        unsigned a[4][4];
        load_A_smemU(a, U, rl0, ch * 32, qc);
        mma_gate(Cc, a, g_pkall + (size_t)(PK_URC0 + 4 + ch) * 2048, lane);
    }
#pragma unroll
    for (int f = 0; f < 8; f++) {
        int col = 8 * f + 2 * qc;
#pragma unroll
        for (int half = 0; half < 2; half++) {
            int rl = rl0 + 8 * half;
            int row = blockIdx.x * 64 + rl;
            float hv0 = Cr[f][2 * half + 0], hv1 = Cr[f][2 * half + 1];
            float c0 = tanhf(Cc[f][2 * half + 0]);
            float c1 = tanhf(Cc[f][2 * half + 1]);
            float u0 = Cu[f][2 * half + 0], u1 = Cu[f][2 * half + 1];
            float o0 = u0 * hv0 + (1.f - u0) * c0;
            float o1 = u1 * hv1 + (1.f - u1) * c1;
            if (row < Nn) *(float2*)(h + (size_t)row * 64 + col) = make_float2(o0, o1);
            U[col * 72 + rl] = f2tf32(o0);
            U[(col + 1) * 72 + rl] = f2tf32(o1);
        }
    }
    __syncwarp();
    float Cx[8][4] = {};
    for (int ch = 0; ch < 2; ch++) {
        unsigned a[4][4];
        load_A_smemU(a, U, rl0, ch * 32, qc);
        mma_gate(Cx, a, g_pkall + (size_t)(PK_WG1 + ch) * 2048, lane);
    }
#pragma unroll
    for (int f = 0; f < 8; f++) {
        int col = 8 * f + 2 * qc;
        if (v0) *(float2*)(xw + (size_t)r0 * 64 + col) = make_float2(Cx[f][0], Cx[f][1]);
        if (v1) *(float2*)(xw + (size_t)r1 * 64 + col) = make_float2(Cx[f][2], Cx[f][3]);
    }
}

// ---------------- layer1 urc + GRU update (pipelined K=192) ------------------
__global__ __launch_bounds__(128, 3) void k_urc1m(
    const float* __restrict__ h0,
    const float* __restrict__ bu, const float* __restrict__ br,
    const float* __restrict__ bc,
    float* __restrict__ h, float* __restrict__ hseq) {
    __shared__ unsigned U[64 * 72];
    int tid = threadIdx.x, lane = tid & 31, w = tid >> 5;
    int qr = lane >> 2, qc = lane & 3;
    int rl0 = w * 16 + qr;
    int r0 = blockIdx.x * 64 + rl0, r1 = r0 + 8;
    bool v0 = r0 < Nn, v1 = r1 < Nn;
    float Cu[8][4] = {}, Cr[8][4] = {}, Cc[8][4] = {};
    float araw[16];
    load_A_raw(araw, h0, 64, r0, r1, v0, v1, 0, qc);
#pragma unroll
    for (int ch = 0; ch < 6; ch++) {
        unsigned a[4][4];
        cvt_frag(a, araw);
        if (ch < 5) {
            int cn = ch + 1;
            const float* Sn = (cn < 2) ? h0 : (cn < 4) ? g_gg : h;
            load_A_raw(araw, Sn, 64, r0, r1, v0, v1, (cn & 1) * 32, qc);
        }
        mma_gate(Cu, a, g_pkall + (size_t)(PK_URC1 + ch) * 2048, lane);
        mma_gate(Cr, a, g_pkall + (size_t)(PK_URC1 + 6 + ch) * 2048, lane);
        if (ch < 4) mma_gate(Cc, a, g_pkall + (size_t)(PK_URC1 + 12 + ch) * 2048, lane);
    }
#pragma unroll
    for (int f = 0; f < 8; f++) {
        int col = 8 * f + 2 * qc;
        float2 bu2 = *(const float2*)(bu + col);
        float2 br2 = *(const float2*)(br + col);
#pragma unroll
        for (int half = 0; half < 2; half++) {
            int rl = rl0 + 8 * half;
            int row = blockIdx.x * 64 + rl;
            float u0 = sigmoidf_(Cu[f][2 * half + 0] + bu2.x);
            float u1 = sigmoidf_(Cu[f][2 * half + 1] + bu2.y);
            float rg0 = sigmoidf_(Cr[f][2 * half + 0] + br2.x);
            float rg1 = sigmoidf_(Cr[f][2 * half + 1] + br2.y);
            Cu[f][2 * half + 0] = u0;
            Cu[f][2 * half + 1] = u1;
            float2 hv = make_float2(0.f, 0.f);
            if (row < Nn) hv = *(const float2*)(h + (size_t)row * 64 + col);
            Cr[f][2 * half + 0] = hv.x;
            Cr[f][2 * half + 1] = hv.y;
            U[col * 72 + rl] = f2tf32(rg0 * hv.x);
            U[(col + 1) * 72 + rl] = f2tf32(rg1 * hv.y);
        }
    }
    __syncwarp();
    for (int ch = 0; ch < 2; ch++) {
        unsigned a[4][4];
        load_A_smemU(a, U, rl0, ch * 32, qc);
        mma_gate(Cc, a, g_pkall + (size_t)(PK_URC1 + 16 + ch) * 2048, lane);
    }
#pragma unroll
    for (int f = 0; f < 8; f++) {
        int col = 8 * f + 2 * qc;
        float2 bc2 = *(const float2*)(bc + col);
#pragma unroll
        for (int half = 0; half < 2; half++) {
            int row = blockIdx.x * 64 + rl0 + 8 * half;
            if (row >= Nn) continue;
            float hv0 = Cr[f][2 * half + 0], hv1 = Cr[f][2 * half + 1];
            float c0 = tanhf(Cc[f][2 * half + 0] + bc2.x);
            float c1 = tanhf(Cc[f][2 * half + 1] + bc2.y);
            float u0 = Cu[f][2 * half + 0], u1 = Cu[f][2 * half + 1];
            float2 o = make_float2(u0 * hv0 + (1.f - u0) * c0,
                                   u1 * hv1 + (1.f - u1) * c1);
            *(float2*)(h + (size_t)row * 64 + col) = o;
            *(float2*)(hseq + (size_t)row * 64 + col) = o;
        }
    }
}

// ---------------- attention tail -------------------------------------------
__global__ __launch_bounds__(128) void k_attn2(
    const float* __restrict__ opb,
    const float* __restrict__ ow, const float* __restrict__ ob,
    float* __restrict__ out) {
    __shared__ float s_qkv[4][Tt * 192];
    __shared__ float s_sc[4][2 * Tt * Tt];
    __shared__ float s_cs[4][2 * Tt];
    __shared__ float s_ob[4][Hh];
    __shared__ float s_ha[4][Hh];
    int w = threadIdx.x >> 5, lane = threadIdx.x & 31;
    int n = blockIdx.x * 4 + w;
    if (n >= Nn) return;
    float* qkv = s_qkv[w];
    float* sc = s_sc[w];
    float* cs = s_cs[w];
    float* obw = s_ob[w];
    float* haw = s_ha[w];

    for (int i = lane; i < Tt * 48; i += 32) {
        int t = i / 48, r = i % 48;
        *(float4*)&qkv[t * 192 + r * 4] =
            *(const float4*)&g_qkv[((size_t)t * Nn + n) * 192 + r * 4];
    }
    __syncwarp();
    for (int idx = lane; idx < 2 * Tt * Tt; idx += 32) {
        int hd = idx / (Tt * Tt);
        int r = idx % (Tt * Tt);
        int t = r / Tt, s = r % Tt;
        const float* qp = &qkv[t * 192 + hd * 32];
        const float* kp = &qkv[s * 192 + 64 + hd * 32];
        float a = 0.f;
#pragma unroll
        for (int d = 0; d < 32; d++) a += qp[d] * kp[d];
        sc[idx] = a * 0.17677669529663687f;
    }
    __syncwarp();
    if (lane < 2 * Tt) {
        float* row = &sc[lane * Tt];
        float mx = row[0];
#pragma unroll
        for (int s = 1; s < Tt; s++) mx = fmaxf(mx, row[s]);
        float sum = 0.f;
#pragma unroll
        for (int s = 0; s < Tt; s++) { float e = __expf(row[s] - mx); row[s] = e; sum += e; }
        float inv = 1.0f / sum;
#pragma unroll
        for (int s = 0; s < Tt; s++) row[s] *= inv;
    }
    __syncwarp();
    if (lane < 2 * Tt) {
        int hd = lane / Tt, s = lane % Tt;
        float a = 0.f;
#pragma unroll
        for (int t = 0; t < Tt; t++) a += sc[hd * Tt * Tt + t * Tt + s];
        cs[lane] = a * (1.0f / 12.0f);
    }
    __syncwarp();
    for (int m = 0; m < 2; m++) {
        int j = lane + 32 * m;
        int hd = j >> 5;
        float a = 0.f;
#pragma unroll
        for (int s = 0; s < Tt; s++) a += cs[hd * Tt + s] * qkv[s * 192 + 128 + j];
        obw[j] = a;
    }
    __syncwarp();
    for (int m = 0; m < 2; m++) {
        int i = lane + 32 * m;
        float a = opb[i];
#pragma unroll
        for (int j = 0; j < Hh; j++) a += g_opwT[j * Hh + i] * obw[j];
        haw[i] = a;
    }
    __syncwarp();
    if (lane < OUTD) {
        float a = ob[lane];
#pragma unroll
        for (int i = 0; i < Hh; i++) a += haw[i] * ow[(size_t)i * OUTD + lane];
        out[(size_t)n * OUTD + lane] = a;
    }
}

// ---------------- host ----------------
extern "C" void kernel_launch(void* const* d_in, const int* in_sizes, int n_in,
                              void* d_out, int out_size) {
    (void)in_sizes; (void)n_in; (void)out_size;
    const float* x   = (const float*)d_in[0];
    const int*   ei  = (const int*)d_in[1];
    const float* ea  = (const float*)d_in[2];
    const float* Wg0 = (const float*)d_in[3];
    const float* bg0 = (const float*)d_in[4];
    const float* Wu0 = (const float*)d_in[5];
    const float* bu0 = (const float*)d_in[6];
    const float* Wr0 = (const float*)d_in[7];
    const float* br0 = (const float*)d_in[8];
    const float* Wc0 = (const float*)d_in[9];
    const float* bc0 = (const float*)d_in[10];
    const float* Wg1 = (const float*)d_in[11];
    const float* bg1 = (const float*)d_in[12];
    const float* Wu1 = (const float*)d_in[13];
    const float* bu1 = (const float*)d_in[14];
    const float* Wr1 = (const float*)d_in[15];
    const float* br1 = (const float*)d_in[16];
    const float* Wc1 = (const float*)d_in[17];
    const float* bc1 = (const float*)d_in[18];
    const float* ipw = (const float*)d_in[19];
    const float* ipb = (const float*)d_in[20];
    const float* opw = (const float*)d_in[21];
    const float* opb = (const float*)d_in[22];
    const float* ow  = (const float*)d_in[23];
    const float* ob  = (const float*)d_in[24];
    float* out = (float*)d_out;

    void *p_deg, *p_cnt, *p_cur, *p_h0, *p_h1, *p_xt, *p_hseq;
    void *p_xw0all, *p_p0all, *p_xw, *p_ipwT, *p_pkall;
    cudaGetSymbolAddress(&p_deg, g_deg);
    cudaGetSymbolAddress(&p_cnt, g_cnt);
    cudaGetSymbolAddress(&p_cur, g_cur);
    cudaGetSymbolAddress(&p_h0, g_h0);
    cudaGetSymbolAddress(&p_h1, g_h1);
    cudaGetSymbolAddress(&p_xt, g_xt);
    cudaGetSymbolAddress(&p_hseq, g_hseq);
    cudaGetSymbolAddress(&p_xw0all, g_xw0all);
    cudaGetSymbolAddress(&p_p0all, g_p0all);
    cudaGetSymbolAddress(&p_xw, g_xw);
    cudaGetSymbolAddress(&p_ipwT, g_ipwT);
    cudaGetSymbolAddress(&p_pkall, g_pkall);

    cudaMemsetAsync(p_deg, 0, Nn * sizeof(float), 0);
    cudaMemsetAsync(p_cnt, 0, Nn * sizeof(int), 0);
    cudaMemsetAsync(p_cur, 0, Nn * sizeof(int), 0);
    cudaMemsetAsync(p_h0, 0, (size_t)Nn * Hh * sizeof(float), 0);
    cudaMemsetAsync(p_h1, 0, (size_t)Nn * Hh * sizeof(float), 0);

    k_prep<<<TB0 + TB1 + TB2, 256>>>(x, ipw, opw, ei, ea);
    k_scan<<<1, 1024>>>();                       // fast scan + dinv
    k_fill<<<(Ee + 255) / 256, 256>>>(ei, ea);   // fill + norm

    // ---- single-launch weight packing ----
    float* ipwT = (float*)p_ipwT;
    PackTab tab;
    int gi = 0;
    tab.src[gi] = Wg0; tab.ldw[gi++] = 64;
    const float* Ws0[3] = {Wu0, Wr0, Wc0};
    for (int g = 0; g < 3; g++)
        for (int c = 0; c < 3; c++) { tab.src[gi] = Ws0[g] + (size_t)c * 32 * 64; tab.ldw[gi++] = 64; }
    for (int g = 0; g < 3; g++)
        for (int c = 0; c < 2; c++) { tab.src[gi] = Ws0[g] + (size_t)(96 + c * 32) * 64; tab.ldw[gi++] = 64; }
    for (int c = 0; c < 2; c++) { tab.src[gi] = Wg1 + (size_t)c * 32 * 64; tab.ldw[gi++] = 64; }
    const float* Ws1[3] = {Wu1, Wr1, Wc1};
    for (int g = 0; g < 3; g++)
        for (int c = 0; c < 6; c++) { tab.src[gi] = Ws1[g] + (size_t)c * 32 * 64; tab.ldw[gi++] = 64; }
    for (int g = 0; g < 3; g++)
        for (int c = 0; c < 2; c++) { tab.src[gi] = ipwT + g * 64 + (size_t)c * 32 * 192; tab.ldw[gi++] = 192; }
    k_packall<<<(42 * 512 + 255) / 256, 256>>>(tab);

    // ---- hoisted precomputes ----
    k_mma_g<<<TN / 128, 256>>>((const float*)p_xt, Ff, 1, TN,
                               (const unsigned*)p_pkall + (size_t)PK_WG0 * 2048, (float*)p_xw0all);
    k_agg_all<<<(TN + 7) / 8, 256>>>(bg0);
    k_pre0m<<<TN / 128, 256>>>(bu0, br0, bc0);

    const int AGG_GRID = (Nn + 7) / 8;
    float* h0 = (float*)p_h0;
    float* h1 = (float*)p_h1;
    float* xw = (float*)p_xw;
    const float* p0all = (const float*)p_p0all;

    for (int t = 0; t < Tt; t++) {
        k_urc0x<<<GB, 128>>>(p0all + (size_t)t * Nn * 192, h0, xw);
        k_gcn_agg<<<AGG_GRID, 256>>>(bg1);
        k_urc1m<<<GB, 128>>>(h0, bu1, br1, bc1, h1,
                             (float*)p_hseq + (size_t)t * Nn * Hh);
    }

    k_qkvm<<<TN / 128, 256>>>(ipb);
    k_attn2<<<(Nn + 3) / 4, 128>>>(opb, ow, ob, out);
}

// round 15
// speedup vs baseline: 1.0344x; 1.0138x over previous
#include <cuda_runtime.h>
#include <math.h>
#include <stdint.h>

#define Nn 20000
#define Ff 32
#define Tt 12
#define Hh 64
#define Ee 320000
#define OUTD 12
#define TN (Tt * Nn)
#define GB 313

// ---------------- scratch ----------------
static __device__ float g_xt[(size_t)TN * Ff];
static __device__ float g_deg[Nn];
static __device__ float g_dinv[Nn];
static __device__ int   g_cnt[Nn];
static __device__ int   g_cur[Nn];
static __device__ int   g_rowptr[Nn + 1];
static __device__ int   g_csrsrc[Ee];
static __device__ float g_csrnorm[Ee];
static __device__ float g_aggx[(size_t)TN * Ff];     // (A_hat x) for all t
static __device__ float g_g0all[(size_t)TN * Hh];
static __device__ float g_p0all[(size_t)TN * 192];
static __device__ float g_xw[(size_t)Nn * Hh];
static __device__ float g_gg[(size_t)Nn * Hh];
static __device__ float g_h0[(size_t)Nn * Hh];
static __device__ float g_h1[(size_t)Nn * Hh];
static __device__ float g_hseq[(size_t)TN * Hh];
static __device__ float g_qkv[(size_t)TN * 192];
static __device__ float g_ipwT[Hh * 192];
static __device__ float g_opwT[Hh * Hh];

// unified pre-packed tf32 b-fragments: 42 chunks x 2048 unsigned
static __device__ unsigned g_pkall[42 * 2048];
#define PK_WG0  0
#define PK_PRE0 1
#define PK_URC0 10
#define PK_WG1  16
#define PK_URC1 18
#define PK_QKV  36

struct PackTab { const float* src[42]; int ldw[42]; };

__device__ __forceinline__ float sigmoidf_(float x) { return 1.0f / (1.0f + __expf(-x)); }

__device__ __forceinline__ unsigned f2tf32(float f) {
    unsigned r;
    asm("cvt.rna.tf32.f32 %0, %1;" : "=r"(r) : "f"(f));
    return r;
}

__device__ __forceinline__ void mma_tf32(float c[4], const unsigned a[4], unsigned b0, unsigned b1) {
    asm volatile(
        "mma.sync.aligned.m16n8k8.row.col.f32.tf32.tf32.f32 "
        "{%0,%1,%2,%3}, {%4,%5,%6,%7}, {%8,%9}, {%0,%1,%2,%3};"
        : "+f"(c[0]), "+f"(c[1]), "+f"(c[2]), "+f"(c[3])
        : "r"(a[0]), "r"(a[1]), "r"(a[2]), "r"(a[3]), "r"(b0), "r"(b1));
}

__device__ __forceinline__ void load_A_raw(float x[16], const float* __restrict__ A,
                                           int lda, int r0, int r1, bool v0, bool v1,
                                           int k0, int qc) {
#pragma unroll
    for (int s = 0; s < 4; s++) {
        int k = k0 + 8 * s + qc;
        x[4 * s + 0] = v0 ? A[(size_t)r0 * lda + k] : 0.f;
        x[4 * s + 1] = v1 ? A[(size_t)r1 * lda + k] : 0.f;
        x[4 * s + 2] = v0 ? A[(size_t)r0 * lda + k + 4] : 0.f;
        x[4 * s + 3] = v1 ? A[(size_t)r1 * lda + k + 4] : 0.f;
    }
}

__device__ __forceinline__ void cvt_frag(unsigned a[4][4], const float x[16]) {
#pragma unroll
    for (int s = 0; s < 4; s++)
#pragma unroll
        for (int j = 0; j < 4; j++) a[s][j] = f2tf32(x[4 * s + j]);
}

__device__ __forceinline__ void load_A_chunk(unsigned a[4][4], const float* __restrict__ A,
                                             int lda, int r0, int r1, bool v0, bool v1,
                                             int k0, int qc) {
    float x[16];
    load_A_raw(x, A, lda, r0, r1, v0, v1, k0, qc);
    cvt_frag(a, x);
}

__device__ __forceinline__ void load_A_smemU(unsigned a[4][4], const unsigned* U,
                                             int rl0, int k0, int qc) {
#pragma unroll
    for (int s = 0; s < 4; s++) {
        int k = k0 + 8 * s + qc;
        a[s][0] = U[k * 72 + rl0];
        a[s][1] = U[k * 72 + rl0 + 8];
        a[s][2] = U[(k + 4) * 72 + rl0];
        a[s][3] = U[(k + 4) * 72 + rl0 + 8];
    }
}

__device__ __forceinline__ void mma_gate(float C[8][4], const unsigned a[4][4],
                                         const unsigned* __restrict__ Bpk, int lane) {
    const uint4* B4 = (const uint4*)Bpk;
#pragma unroll
    for (int s = 0; s < 4; s++)
#pragma unroll
        for (int f2 = 0; f2 < 4; f2++) {
            uint4 b = B4[(s * 4 + f2) * 32 + lane];
            mma_tf32(C[2 * f2], a[s], b.x, b.y);
            mma_tf32(C[2 * f2 + 1], a[s], b.z, b.w);
        }
}

// ---------------- single-launch weight pack ----------------------------------
__global__ void k_packall(PackTab tab) {
    int tid = blockIdx.x * blockDim.x + threadIdx.x;
    if (tid >= 42 * 512) return;
    int g = tid >> 9, r = tid & 511;
    const float* W = tab.src[g];
    int ldw = tab.ldw[g];
    int s = r >> 7, f2 = (r >> 5) & 3, lane = r & 31;
    int qr = lane >> 2, qc = lane & 3;
    int k1 = 8 * s + qc, k2 = k1 + 4;
    int n1 = 16 * f2 + qr, n2 = n1 + 8;
    uint4 o;
    o.x = f2tf32(W[(size_t)k1 * ldw + n1]);
    o.y = f2tf32(W[(size_t)k2 * ldw + n1]);
    o.z = f2tf32(W[(size_t)k1 * ldw + n2]);
    o.w = f2tf32(W[(size_t)k2 * ldw + n2]);
    ((uint4*)g_pkall)[tid] = o;
}

// ---------------- merged elementwise preproc ---------------------------------
#define TB0 ((Nn * Ff * Tt + 255) / 256)
#define TB1 48
#define TB2 ((Ee + 255) / 256)
__global__ void k_prep(const float* __restrict__ x,
                       const float* __restrict__ ipw, const float* __restrict__ opw,
                       const int* __restrict__ ei, const float* __restrict__ ea) {
    int b = blockIdx.x;
    if (b < TB0) {
        int idx = b * 256 + threadIdx.x;
        if (idx >= Nn * Ff * Tt) return;
        int f = idx & (Ff - 1);
        int t = (idx / Ff) % Tt;
        int n = idx / (Ff * Tt);
        g_xt[(size_t)t * Nn * Ff + (size_t)n * Ff + f] =
            x[(size_t)n * Ff * Tt + (size_t)f * Tt + t];
    } else if (b < TB0 + TB1) {
        int i = (b - TB0) * 256 + threadIdx.x;
        if (i < 192 * Hh) { int r = i / Hh, c = i % Hh; g_ipwT[c * 192 + r] = ipw[i]; }
        if (i < Hh * Hh)  { int r = i / Hh, c = i % Hh; g_opwT[c * Hh + r] = opw[i]; }
    } else {
        int e = (b - TB0 - TB1) * 256 + threadIdx.x;
        if (e >= Ee) return;
        int d = ei[Ee + e];
        atomicAdd(&g_deg[d], ea[2 * e + 1]);
        atomicAdd(&g_cnt[d], 1);
    }
}

// ---------------- fast scan (shuffle-based) + fused dinv ----------------------
__global__ __launch_bounds__(1024) void k_scan() {
    const int ELT = 20;
    int tid = threadIdx.x;
    int base = tid * ELT;
    int v[ELT];
    int sum = 0;
#pragma unroll
    for (int i = 0; i < ELT; i++) {
        int idx = base + i;
        v[i] = (idx < Nn) ? g_cnt[idx] : 0;
        sum += v[i];
    }
    int lane = tid & 31, wid = tid >> 5;
    int s = sum;
#pragma unroll
    for (int off = 1; off < 32; off <<= 1) {
        int t2 = __shfl_up_sync(0xffffffffu, s, off);
        if (lane >= off) s += t2;
    }
    __shared__ int wsum[32];
    if (lane == 31) wsum[wid] = s;
    __syncthreads();
    if (wid == 0) {
        int ws = wsum[lane];
#pragma unroll
        for (int off = 1; off < 32; off <<= 1) {
            int t2 = __shfl_up_sync(0xffffffffu, ws, off);
            if (lane >= off) ws += t2;
        }
        wsum[lane] = ws;
    }
    __syncthreads();
    int offset = ((wid > 0) ? wsum[wid - 1] : 0) + (s - sum);
    if (tid == 0) g_rowptr[0] = 0;
    int run = offset;
#pragma unroll
    for (int i = 0; i < ELT; i++) {
        run += v[i];
        int idx = base + i;
        if (idx < Nn) g_rowptr[idx + 1] = run;
    }
    for (int n = tid; n < Nn; n += 1024)
        g_dinv[n] = rsqrtf(g_deg[n] + 1.0f);
}

// fill + fused norm computation
__global__ void k_fill(const int* __restrict__ ei, const float* __restrict__ ea) {
    int e = blockIdx.x * blockDim.x + threadIdx.x;
    if (e >= Ee) return;
    int s = ei[e], d = ei[Ee + e];
    int pos = g_rowptr[d] + atomicAdd(&g_cur[d], 1);
    g_csrsrc[pos] = s;
    g_csrnorm[pos] = g_dinv[s] * ea[2 * e + 1] * g_dinv[d];
}

// ---------------- raw-feature GCN aggregate for all t (F=32, half traffic) ---
__global__ void k_aggx_all() {
    int gw = blockIdx.x * (blockDim.x >> 5) + (threadIdx.x >> 5);
    if (gw >= TN) return;
    int t = gw / Nn, n = gw - t * Nn;
    int lane = threadIdx.x & 31;
    const float* xs = g_xt + (size_t)t * Nn * Ff;
    int beg = g_rowptr[n], end = g_rowptr[n + 1];
    float a0 = 0.f;
#pragma unroll 4
    for (int p = beg; p < end; p++) {
        int s = g_csrsrc[p];
        float nm = g_csrnorm[p];
        a0 += nm * xs[(size_t)s * Ff + lane];
    }
    float dv = g_dinv[n];
    a0 += dv * dv * xs[(size_t)n * Ff + lane];
    g_aggx[(size_t)gw * Ff + lane] = a0;
}

// ---------------- g0 = sigmoid(aggx @ Wg0 + bg0)  (K=32, fused epilogue) -----
__global__ __launch_bounds__(256) void k_g0m(const float* __restrict__ bg) {
    int tid = threadIdx.x, lane = tid & 31, w = tid >> 5;
    int qr = lane >> 2, qc = lane & 3;
    int r0 = blockIdx.x * 128 + w * 16 + qr, r1 = r0 + 8;   // TN % 128 == 0
    float C[8][4] = {};
    unsigned a[4][4];
    load_A_chunk(a, g_aggx, Ff, r0, r1, true, true, 0, qc);
    mma_gate(C, a, g_pkall + (size_t)PK_WG0 * 2048, lane);
#pragma unroll
    for (int f = 0; f < 8; f++) {
        int col = 8 * f + 2 * qc;
        float2 b2 = *(const float2*)(bg + col);
        *(float2*)(g_g0all + (size_t)r0 * 64 + col) =
            make_float2(sigmoidf_(C[f][0] + b2.x), sigmoidf_(C[f][1] + b2.y));
        *(float2*)(g_g0all + (size_t)r1 * 64 + col) =
            make_float2(sigmoidf_(C[f][2] + b2.x), sigmoidf_(C[f][3] + b2.y));
    }
}

// ---------------- pre0 (128-row, 3 gates share A) ---------------------------
__global__ __launch_bounds__(256) void k_pre0m(const float* __restrict__ bu,
                                               const float* __restrict__ br,
                                               const float* __restrict__ bc) {
    int tid = threadIdx.x, lane = tid & 31, w = tid >> 5;
    int qr = lane >> 2, qc = lane & 3;
    int r0 = blockIdx.x * 128 + w * 16 + qr, r1 = r0 + 8;   // TN % 128 == 0
    float C[3][8][4] = {};
    for (int ch = 0; ch < 3; ch++) {
        const float* S = ch ? g_g0all : g_xt;
        int lda = ch ? 64 : 32;
        int k0 = (ch == 2) ? 32 : 0;
        unsigned a[4][4];
        load_A_chunk(a, S, lda, r0, r1, true, true, k0, qc);
#pragma unroll
        for (int g = 0; g < 3; g++)
            mma_gate(C[g], a, g_pkall + (size_t)(PK_PRE0 + g * 3 + ch) * 2048, lane);
    }
#pragma unroll
    for (int g = 0; g < 3; g++) {
        const float* b = (g == 0) ? bu : (g == 1) ? br : bc;
#pragma unroll
        for (int f = 0; f < 8; f++) {
            int col = 8 * f + 2 * qc;
            float2 b2 = *(const float2*)(b + col);
            *(float2*)(g_p0all + (size_t)r0 * 192 + g * 64 + col) =
                make_float2(C[g][f][0] + b2.x, C[g][f][1] + b2.y);
            *(float2*)(g_p0all + (size_t)r1 * 192 + g * 64 + col) =
                make_float2(C[g][f][2] + b2.x, C[g][f][3] + b2.y);
        }
    }
}

// ---------------- qkv (128-row) ----------------------------------------------
__global__ __launch_bounds__(256) void k_qkvm(const float* __restrict__ ipb) {
    int tid = threadIdx.x, lane = tid & 31, w = tid >> 5;
    int qr = lane >> 2, qc = lane & 3;
    int r0 = blockIdx.x * 128 + w * 16 + qr, r1 = r0 + 8;
    float C[3][8][4] = {};
    for (int ch = 0; ch < 2; ch++) {
        unsigned a[4][4];
        load_A_chunk(a, g_hseq, 64, r0, r1, true, true, ch * 32, qc);
#pragma unroll
        for (int g = 0; g < 3; g++)
            mma_gate(C[g], a, g_pkall + (size_t)(PK_QKV + g * 2 + ch) * 2048, lane);
    }
#pragma unroll
    for (int g = 0; g < 3; g++) {
#pragma unroll
        for (int f = 0; f < 8; f++) {
            int col = 8 * f + 2 * qc;
            float2 b2 = *(const float2*)(ipb + g * 64 + col);
            *(float2*)(g_qkv + (size_t)r0 * 192 + g * 64 + col) =
                make_float2(C[g][f][0] + b2.x, C[g][f][1] + b2.y);
            *(float2*)(g_qkv + (size_t)r1 * 192 + g * 64 + col) =
                make_float2(C[g][f][2] + b2.x, C[g][f][3] + b2.y);
        }
    }
}

// ---------------- per-step GCN agg (layer1, 1 warp/node, 0 smem) -------------
__global__ void k_gcn_agg(const float* __restrict__ bg) {
    int n = blockIdx.x * (blockDim.x >> 5) + (threadIdx.x >> 5);
    if (n >= Nn) return;
    int lane = threadIdx.x & 31;
    int beg = g_rowptr[n], end = g_rowptr[n + 1];
    float a0 = 0.f, a1 = 0.f;
#pragma unroll 4
    for (int p = beg; p < end; p++) {
        int s = g_csrsrc[p];
        float nm = g_csrnorm[p];
        a0 += nm * g_xw[(size_t)s * Hh + lane];
        a1 += nm * g_xw[(size_t)s * Hh + lane + 32];
    }
    float dv = g_dinv[n];
    float dd = dv * dv;
    a0 += dd * g_xw[(size_t)n * Hh + lane] + bg[lane];
    a1 += dd * g_xw[(size_t)n * Hh + lane + 32] + bg[lane + 32];
    g_gg[(size_t)n * Hh + lane] = sigmoidf_(a0);
    g_gg[(size_t)n * Hh + lane + 32] = sigmoidf_(a1);
}

// ---------------- layer0 urc + GRU update + xw=h@Wg1 (pipelined) -------------
__global__ __launch_bounds__(128, 3) void k_urc0x(const float* __restrict__ p0,
                                                  float* __restrict__ h,
                                                  float* __restrict__ xw) {
    __shared__ unsigned U[64 * 72];
    int tid = threadIdx.x, lane = tid & 31, w = tid >> 5;
    int qr = lane >> 2, qc = lane & 3;
    int rl0 = w * 16 + qr;
    int r0 = blockIdx.x * 64 + rl0, r1 = r0 + 8;
    bool v0 = r0 < Nn, v1 = r1 < Nn;
    float araw[16];
    load_A_raw(araw, h, 64, r0, r1, v0, v1, 0, qc);
    float Cu[8][4], Cr[8][4], Cc[8][4];
#pragma unroll
    for (int f = 0; f < 8; f++) {
        int col = 8 * f + 2 * qc;
        float2 z = make_float2(0.f, 0.f);
        float2 u0 = z, u1 = z, rr0 = z, rr1 = z, c0 = z, c1 = z;
        if (v0) {
            u0  = *(const float2*)(p0 + (size_t)r0 * 192 + col);
            rr0 = *(const float2*)(p0 + (size_t)r0 * 192 + 64 + col);
            c0  = *(const float2*)(p0 + (size_t)r0 * 192 + 128 + col);
        }
        if (v1) {
            u1  = *(const float2*)(p0 + (size_t)r1 * 192 + col);
            rr1 = *(const float2*)(p0 + (size_t)r1 * 192 + 64 + col);
            c1  = *(const float2*)(p0 + (size_t)r1 * 192 + 128 + col);
        }
        Cu[f][0] = u0.x;  Cu[f][1] = u0.y;  Cu[f][2] = u1.x;  Cu[f][3] = u1.y;
        Cr[f][0] = rr0.x; Cr[f][1] = rr0.y; Cr[f][2] = rr1.x; Cr[f][3] = rr1.y;
        Cc[f][0] = c0.x;  Cc[f][1] = c0.y;  Cc[f][2] = c1.x;  Cc[f][3] = c1.y;
    }
#pragma unroll
    for (int ch = 0; ch < 2; ch++) {
        unsigned a[4][4];
        cvt_frag(a, araw);
        if (ch == 0) load_A_raw(araw, h, 64, r0, r1, v0, v1, 32, qc);
        mma_gate(Cu, a, g_pkall + (size_t)(PK_URC0 + 0 + ch) * 2048, lane);
        mma_gate(Cr, a, g_pkall + (size_t)(PK_URC0 + 2 + ch) * 2048, lane);
    }
#pragma unroll
    for (int f = 0; f < 8; f++) {
        int col = 8 * f + 2 * qc;
#pragma unroll
        for (int half = 0; half < 2; half++) {
            int rl = rl0 + 8 * half;
            int row = blockIdx.x * 64 + rl;
            float u0 = sigmoidf_(Cu[f][2 * half + 0]);
            float u1 = sigmoidf_(Cu[f][2 * half + 1]);
            float rg0 = sigmoidf_(Cr[f][2 * half + 0]);
            float rg1 = sigmoidf_(Cr[f][2 * half + 1]);
            Cu[f][2 * half + 0] = u0;
            Cu[f][2 * half + 1] = u1;
            float2 hv = make_float2(0.f, 0.f);
            if (row < Nn) hv = *(const float2*)(h + (size_t)row * 64 + col);
            Cr[f][2 * half + 0] = hv.x;
            Cr[f][2 * half + 1] = hv.y;
            U[col * 72 + rl] = f2tf32(rg0 * hv.x);
            U[(col + 1) * 72 + rl] = f2tf32(rg1 * hv.y);
        }
    }
    __syncwarp();
    for (int ch = 0; ch < 2; ch++) {
        unsigned a[4][4];
        load_A_smemU(a, U, rl0, ch * 32, qc);
        mma_gate(Cc, a, g_pkall + (size_t)(PK_URC0 + 4 + ch) * 2048, lane);
    }
#pragma unroll
    for (int f = 0; f < 8; f++) {
        int col = 8 * f + 2 * qc;
#pragma unroll
        for (int half = 0; half < 2; half++) {
            int rl = rl0 + 8 * half;
            int row = blockIdx.x * 64 + rl;
            float hv0 = Cr[f][2 * half + 0], hv1 = Cr[f][2 * half + 1];
            float c0 = tanhf(Cc[f][2 * half + 0]);
            float c1 = tanhf(Cc[f][2 * half + 1]);
            float u0 = Cu[f][2 * half + 0], u1 = Cu[f][2 * half + 1];
            float o0 = u0 * hv0 + (1.f - u0) * c0;
            float o1 = u1 * hv1 + (1.f - u1) * c1;
            if (row < Nn) *(float2*)(h + (size_t)row * 64 + col) = make_float2(o0, o1);
            U[col * 72 + rl] = f2tf32(o0);
            U[(col + 1) * 72 + rl] = f2tf32(o1);
        }
    }
    __syncwarp();
    float Cx[8][4] = {};
    for (int ch = 0; ch < 2; ch++) {
        unsigned a[4][4];
        load_A_smemU(a, U, rl0, ch * 32, qc);
        mma_gate(Cx, a, g_pkall + (size_t)(PK_WG1 + ch) * 2048, lane);
    }
#pragma unroll
    for (int f = 0; f < 8; f++) {
        int col = 8 * f + 2 * qc;
        if (v0) *(float2*)(xw + (size_t)r0 * 64 + col) = make_float2(Cx[f][0], Cx[f][1]);
        if (v1) *(float2*)(xw + (size_t)r1 * 64 + col) = make_float2(Cx[f][2], Cx[f][3]);
    }
}

// ---------------- layer1 urc + GRU update (pipelined K=192) ------------------
__global__ __launch_bounds__(128, 3) void k_urc1m(
    const float* __restrict__ h0,
    const float* __restrict__ bu, const float* __restrict__ br,
    const float* __restrict__ bc,
    float* __restrict__ h, float* __restrict__ hseq) {
    __shared__ unsigned U[64 * 72];
    int tid = threadIdx.x, lane = tid & 31, w = tid >> 5;
    int qr = lane >> 2, qc = lane & 3;
    int rl0 = w * 16 + qr;
    int r0 = blockIdx.x * 64 + rl0, r1 = r0 + 8;
    bool v0 = r0 < Nn, v1 = r1 < Nn;
    float Cu[8][4] = {}, Cr[8][4] = {}, Cc[8][4] = {};
    float araw[16];
    load_A_raw(araw, h0, 64, r0, r1, v0, v1, 0, qc);
#pragma unroll
    for (int ch = 0; ch < 6; ch++) {
        unsigned a[4][4];
        cvt_frag(a, araw);
        if (ch < 5) {
            int cn = ch + 1;
            const float* Sn = (cn < 2) ? h0 : (cn < 4) ? g_gg : h;
            load_A_raw(araw, Sn, 64, r0, r1, v0, v1, (cn & 1) * 32, qc);
        }
        mma_gate(Cu, a, g_pkall + (size_t)(PK_URC1 + ch) * 2048, lane);
        mma_gate(Cr, a, g_pkall + (size_t)(PK_URC1 + 6 + ch) * 2048, lane);
        if (ch < 4) mma_gate(Cc, a, g_pkall + (size_t)(PK_URC1 + 12 + ch) * 2048, lane);
    }
#pragma unroll
    for (int f = 0; f < 8; f++) {
        int col = 8 * f + 2 * qc;
        float2 bu2 = *(const float2*)(bu + col);
        float2 br2 = *(const float2*)(br + col);
#pragma unroll
        for (int half = 0; half < 2; half++) {
            int rl = rl0 + 8 * half;
            int row = blockIdx.x * 64 + rl;
            float u0 = sigmoidf_(Cu[f][2 * half + 0] + bu2.x);
            float u1 = sigmoidf_(Cu[f][2 * half + 1] + bu2.y);
            float rg0 = sigmoidf_(Cr[f][2 * half + 0] + br2.x);
            float rg1 = sigmoidf_(Cr[f][2 * half + 1] + br2.y);
            Cu[f][2 * half + 0] = u0;
            Cu[f][2 * half + 1] = u1;
            float2 hv = make_float2(0.f, 0.f);
            if (row < Nn) hv = *(const float2*)(h + (size_t)row * 64 + col);
            Cr[f][2 * half + 0] = hv.x;
            Cr[f][2 * half + 1] = hv.y;
            U[col * 72 + rl] = f2tf32(rg0 * hv.x);
            U[(col + 1) * 72 + rl] = f2tf32(rg1 * hv.y);
        }
    }
    __syncwarp();
    for (int ch = 0; ch < 2; ch++) {
        unsigned a[4][4];
        load_A_smemU(a, U, rl0, ch * 32, qc);
        mma_gate(Cc, a, g_pkall + (size_t)(PK_URC1 + 16 + ch) * 2048, lane);
    }
#pragma unroll
    for (int f = 0; f < 8; f++) {
        int col = 8 * f + 2 * qc;
        float2 bc2 = *(const float2*)(bc + col);
#pragma unroll
        for (int half = 0; half < 2; half++) {
            int row = blockIdx.x * 64 + rl0 + 8 * half;
            if (row >= Nn) continue;
            float hv0 = Cr[f][2 * half + 0], hv1 = Cr[f][2 * half + 1];
            float c0 = tanhf(Cc[f][2 * half + 0] + bc2.x);
            float c1 = tanhf(Cc[f][2 * half + 1] + bc2.y);
            float u0 = Cu[f][2 * half + 0], u1 = Cu[f][2 * half + 1];
            float2 o = make_float2(u0 * hv0 + (1.f - u0) * c0,
                                   u1 * hv1 + (1.f - u1) * c1);
            *(float2*)(h + (size_t)row * 64 + col) = o;
            *(float2*)(hseq + (size_t)row * 64 + col) = o;
        }
    }
}

// ---------------- attention tail -------------------------------------------
__global__ __launch_bounds__(128) void k_attn2(
    const float* __restrict__ opb,
    const float* __restrict__ ow, const float* __restrict__ ob,
    float* __restrict__ out) {
    __shared__ float s_qkv[4][Tt * 192];
    __shared__ float s_sc[4][2 * Tt * Tt];
    __shared__ float s_cs[4][2 * Tt];
    __shared__ float s_ob[4][Hh];
    __shared__ float s_ha[4][Hh];
    int w = threadIdx.x >> 5, lane = threadIdx.x & 31;
    int n = blockIdx.x * 4 + w;
    if (n >= Nn) return;
    float* qkv = s_qkv[w];
    float* sc = s_sc[w];
    float* cs = s_cs[w];
    float* obw = s_ob[w];
    float* haw = s_ha[w];

    for (int i = lane; i < Tt * 48; i += 32) {
        int t = i / 48, r = i % 48;
        *(float4*)&qkv[t * 192 + r * 4] =
            *(const float4*)&g_qkv[((size_t)t * Nn + n) * 192 + r * 4];
    }
    __syncwarp();
    for (int idx = lane; idx < 2 * Tt * Tt; idx += 32) {
        int hd = idx / (Tt * Tt);
        int r = idx % (Tt * Tt);
        int t = r / Tt, s = r % Tt;
        const float* qp = &qkv[t * 192 + hd * 32];
        const float* kp = &qkv[s * 192 + 64 + hd * 32];
        float a = 0.f;
#pragma unroll
        for (int d = 0; d < 32; d++) a += qp[d] * kp[d];
        sc[idx] = a * 0.17677669529663687f;
    }
    __syncwarp();
    if (lane < 2 * Tt) {
        float* row = &sc[lane * Tt];
        float mx = row[0];
#pragma unroll
        for (int s = 1; s < Tt; s++) mx = fmaxf(mx, row[s]);
        float sum = 0.f;
#pragma unroll
        for (int s = 0; s < Tt; s++) { float e = __expf(row[s] - mx); row[s] = e; sum += e; }
        float inv = 1.0f / sum;
#pragma unroll
        for (int s = 0; s < Tt; s++) row[s] *= inv;
    }
    __syncwarp();
    if (lane < 2 * Tt) {
        int hd = lane / Tt, s = lane % Tt;
        float a = 0.f;
#pragma unroll
        for (int t = 0; t < Tt; t++) a += sc[hd * Tt * Tt + t * Tt + s];
        cs[lane] = a * (1.0f / 12.0f);
    }
    __syncwarp();
    for (int m = 0; m < 2; m++) {
        int j = lane + 32 * m;
        int hd = j >> 5;
        float a = 0.f;
#pragma unroll
        for (int s = 0; s < Tt; s++) a += cs[hd * Tt + s] * qkv[s * 192 + 128 + j];
        obw[j] = a;
    }
    __syncwarp();
    for (int m = 0; m < 2; m++) {
        int i = lane + 32 * m;
        float a = opb[i];
#pragma unroll
        for (int j = 0; j < Hh; j++) a += g_opwT[j * Hh + i] * obw[j];
        haw[i] = a;
    }
    __syncwarp();
    if (lane < OUTD) {
        float a = ob[lane];
#pragma unroll
        for (int i = 0; i < Hh; i++) a += haw[i] * ow[(size_t)i * OUTD + lane];
        out[(size_t)n * OUTD + lane] = a;
    }
}

// ---------------- host ----------------
extern "C" void kernel_launch(void* const* d_in, const int* in_sizes, int n_in,
                              void* d_out, int out_size) {
    (void)in_sizes; (void)n_in; (void)out_size;
    const float* x   = (const float*)d_in[0];
    const int*   ei  = (const int*)d_in[1];
    const float* ea  = (const float*)d_in[2];
    const float* Wg0 = (const float*)d_in[3];
    const float* bg0 = (const float*)d_in[4];
    const float* Wu0 = (const float*)d_in[5];
    const float* bu0 = (const float*)d_in[6];
    const float* Wr0 = (const float*)d_in[7];
    const float* br0 = (const float*)d_in[8];
    const float* Wc0 = (const float*)d_in[9];
    const float* bc0 = (const float*)d_in[10];
    const float* Wg1 = (const float*)d_in[11];
    const float* bg1 = (const float*)d_in[12];
    const float* Wu1 = (const float*)d_in[13];
    const float* bu1 = (const float*)d_in[14];
    const float* Wr1 = (const float*)d_in[15];
    const float* br1 = (const float*)d_in[16];
    const float* Wc1 = (const float*)d_in[17];
    const float* bc1 = (const float*)d_in[18];
    const float* ipw = (const float*)d_in[19];
    const float* ipb = (const float*)d_in[20];
    const float* opw = (const float*)d_in[21];
    const float* opb = (const float*)d_in[22];
    const float* ow  = (const float*)d_in[23];
    const float* ob  = (const float*)d_in[24];
    float* out = (float*)d_out;

    void *p_deg, *p_cnt, *p_cur, *p_h0, *p_h1, *p_xt, *p_hseq;
    void *p_p0all, *p_xw, *p_ipwT, *p_pkall;
    cudaGetSymbolAddress(&p_deg, g_deg);
    cudaGetSymbolAddress(&p_cnt, g_cnt);
    cudaGetSymbolAddress(&p_cur, g_cur);
    cudaGetSymbolAddress(&p_h0, g_h0);
    cudaGetSymbolAddress(&p_h1, g_h1);
    cudaGetSymbolAddress(&p_xt, g_xt);
    cudaGetSymbolAddress(&p_hseq, g_hseq);
    cudaGetSymbolAddress(&p_p0all, g_p0all);
    cudaGetSymbolAddress(&p_xw, g_xw);
    cudaGetSymbolAddress(&p_ipwT, g_ipwT);
    cudaGetSymbolAddress(&p_pkall, g_pkall);

    cudaMemsetAsync(p_deg, 0, Nn * sizeof(float), 0);
    cudaMemsetAsync(p_cnt, 0, Nn * sizeof(int), 0);
    cudaMemsetAsync(p_cur, 0, Nn * sizeof(int), 0);
    cudaMemsetAsync(p_h0, 0, (size_t)Nn * Hh * sizeof(float), 0);
    cudaMemsetAsync(p_h1, 0, (size_t)Nn * Hh * sizeof(float), 0);

    k_prep<<<TB0 + TB1 + TB2, 256>>>(x, ipw, opw, ei, ea);
    k_scan<<<1, 1024>>>();
    k_fill<<<(Ee + 255) / 256, 256>>>(ei, ea);

    // ---- single-launch weight packing ----
    float* ipwT = (float*)p_ipwT;
    PackTab tab;
    int gi = 0;
    tab.src[gi] = Wg0; tab.ldw[gi++] = 64;
    const float* Ws0[3] = {Wu0, Wr0, Wc0};
    for (int g = 0; g < 3; g++)
        for (int c = 0; c < 3; c++) { tab.src[gi] = Ws0[g] + (size_t)c * 32 * 64; tab.ldw[gi++] = 64; }
    for (int g = 0; g < 3; g++)
        for (int c = 0; c < 2; c++) { tab.src[gi] = Ws0[g] + (size_t)(96 + c * 32) * 64; tab.ldw[gi++] = 64; }
    for (int c = 0; c < 2; c++) { tab.src[gi] = Wg1 + (size_t)c * 32 * 64; tab.ldw[gi++] = 64; }
    const float* Ws1[3] = {Wu1, Wr1, Wc1};
    for (int g = 0; g < 3; g++)
        for (int c = 0; c < 6; c++) { tab.src[gi] = Ws1[g] + (size_t)c * 32 * 64; tab.ldw[gi++] = 64; }
    for (int g = 0; g < 3; g++)
        for (int c = 0; c < 2; c++) { tab.src[gi] = ipwT + g * 64 + (size_t)c * 32 * 192; tab.ldw[gi++] = 192; }
    k_packall<<<(42 * 512 + 255) / 256, 256>>>(tab);

    // ---- hoisted precomputes: aggregate-then-transform (half gather traffic) --
    k_aggx_all<<<(TN + 7) / 8, 256>>>();
    k_g0m<<<TN / 128, 256>>>(bg0);
    k_pre0m<<<TN / 128, 256>>>(bu0, br0, bc0);

    const int AGG_GRID = (Nn + 7) / 8;
    float* h0 = (float*)p_h0;
    float* h1 = (float*)p_h1;
    float* xw = (float*)p_xw;
    const float* p0all = (const float*)p_p0all;

    for (int t = 0; t < Tt; t++) {
        k_urc0x<<<GB, 128>>>(p0all + (size_t)t * Nn * 192, h0, xw);
        k_gcn_agg<<<AGG_GRID, 256>>>(bg1);
        k_urc1m<<<GB, 128>>>(h0, bu1, br1, bc1, h1,
                             (float*)p_hseq + (size_t)t * Nn * Hh);
    }

    k_qkvm<<<TN / 128, 256>>>(ipb);
    k_attn2<<<(Nn + 3) / 4, 128>>>(opb, ow, ob, out);
}

// round 16
// speedup vs baseline: 1.0607x; 1.0253x over previous
#include <cuda_runtime.h>
#include <math.h>
#include <stdint.h>

#define Nn 20000
#define Ff 32
#define Tt 12
#define Hh 64
#define Ee 320000
#define OUTD 12
#define TN (Tt * Nn)
#define GB 313

// ---------------- scratch ----------------
static __device__ float g_xt[(size_t)TN * Ff];
static __device__ float g_deg[Nn];
static __device__ float g_dinv[Nn];
static __device__ int   g_cnt[Nn];
static __device__ int   g_cur[Nn];
static __device__ int   g_rowptr[Nn + 1];
static __device__ int   g_csrsrc[Ee];
static __device__ float g_csrnorm[Ee];
static __device__ float g_aggx[(size_t)TN * Ff];     // (A_hat x) for all t
static __device__ float g_p0all[(size_t)TN * 192];
static __device__ float g_xw[(size_t)Nn * Hh];
static __device__ float g_gg[(size_t)Nn * Hh];
static __device__ float g_h0[(size_t)Nn * Hh];
static __device__ float g_h1[(size_t)Nn * Hh];
static __device__ float g_qkv[(size_t)TN * 192];
static __device__ float g_ipwT[Hh * 192];
static __device__ float g_opwT[Hh * Hh];

// unified pre-packed tf32 b-fragments: 42 chunks x 2048 unsigned
static __device__ unsigned g_pkall[42 * 2048];
#define PK_WG0  0
#define PK_PRE0 1
#define PK_URC0 10
#define PK_WG1  16
#define PK_URC1 18
#define PK_QKV  36

struct PackTab { const float* src[42]; int ldw[42]; };

__device__ __forceinline__ float sigmoidf_(float x) { return 1.0f / (1.0f + __expf(-x)); }

__device__ __forceinline__ unsigned f2tf32(float f) {
    unsigned r;
    asm("cvt.rna.tf32.f32 %0, %1;" : "=r"(r) : "f"(f));
    return r;
}

__device__ __forceinline__ void mma_tf32(float c[4], const unsigned a[4], unsigned b0, unsigned b1) {
    asm volatile(
        "mma.sync.aligned.m16n8k8.row.col.f32.tf32.tf32.f32 "
        "{%0,%1,%2,%3}, {%4,%5,%6,%7}, {%8,%9}, {%0,%1,%2,%3};"
        : "+f"(c[0]), "+f"(c[1]), "+f"(c[2]), "+f"(c[3])
        : "r"(a[0]), "r"(a[1]), "r"(a[2]), "r"(a[3]), "r"(b0), "r"(b1));
}

__device__ __forceinline__ void load_A_raw(float x[16], const float* __restrict__ A,
                                           int lda, int r0, int r1, bool v0, bool v1,
                                           int k0, int qc) {
#pragma unroll
    for (int s = 0; s < 4; s++) {
        int k = k0 + 8 * s + qc;
        x[4 * s + 0] = v0 ? A[(size_t)r0 * lda + k] : 0.f;
        x[4 * s + 1] = v1 ? A[(size_t)r1 * lda + k] : 0.f;
        x[4 * s + 2] = v0 ? A[(size_t)r0 * lda + k + 4] : 0.f;
        x[4 * s + 3] = v1 ? A[(size_t)r1 * lda + k + 4] : 0.f;
    }
}

__device__ __forceinline__ void cvt_frag(unsigned a[4][4], const float x[16]) {
#pragma unroll
    for (int s = 0; s < 4; s++)
#pragma unroll
        for (int j = 0; j < 4; j++) a[s][j] = f2tf32(x[4 * s + j]);
}

__device__ __forceinline__ void load_A_chunk(unsigned a[4][4], const float* __restrict__ A,
                                             int lda, int r0, int r1, bool v0, bool v1,
                                             int k0, int qc) {
    float x[16];
    load_A_raw(x, A, lda, r0, r1, v0, v1, k0, qc);
    cvt_frag(a, x);
}

__device__ __forceinline__ void load_A_smemU(unsigned a[4][4], const unsigned* U,
                                             int rl0, int k0, int qc) {
#pragma unroll
    for (int s = 0; s < 4; s++) {
        int k = k0 + 8 * s + qc;
        a[s][0] = U[k * 72 + rl0];
        a[s][1] = U[k * 72 + rl0 + 8];
        a[s][2] = U[(k + 4) * 72 + rl0];
        a[s][3] = U[(k + 4) * 72 + rl0 + 8];
    }
}

__device__ __forceinline__ void mma_gate(float C[8][4], const unsigned a[4][4],
                                         const unsigned* __restrict__ Bpk, int lane) {
    const uint4* B4 = (const uint4*)Bpk;
#pragma unroll
    for (int s = 0; s < 4; s++)
#pragma unroll
        for (int f2 = 0; f2 < 4; f2++) {
            uint4 b = B4[(s * 4 + f2) * 32 + lane];
            mma_tf32(C[2 * f2], a[s], b.x, b.y);
            mma_tf32(C[2 * f2 + 1], a[s], b.z, b.w);
        }
}

// ---------------- single-launch weight pack ----------------------------------
__global__ void k_packall(PackTab tab) {
    int tid = blockIdx.x * blockDim.x + threadIdx.x;
    if (tid >= 42 * 512) return;
    int g = tid >> 9, r = tid & 511;
    const float* W = tab.src[g];
    int ldw = tab.ldw[g];
    int s = r >> 7, f2 = (r >> 5) & 3, lane = r & 31;
    int qr = lane >> 2, qc = lane & 3;
    int k1 = 8 * s + qc, k2 = k1 + 4;
    int n1 = 16 * f2 + qr, n2 = n1 + 8;
    uint4 o;
    o.x = f2tf32(W[(size_t)k1 * ldw + n1]);
    o.y = f2tf32(W[(size_t)k2 * ldw + n1]);
    o.z = f2tf32(W[(size_t)k1 * ldw + n2]);
    o.w = f2tf32(W[(size_t)k2 * ldw + n2]);
    ((uint4*)g_pkall)[tid] = o;
}

// ---------------- merged elementwise preproc ---------------------------------
#define TB0 ((Nn * Ff * Tt + 255) / 256)
#define TB1 48
#define TB2 ((Ee + 255) / 256)
__global__ void k_prep(const float* __restrict__ x,
                       const float* __restrict__ ipw, const float* __restrict__ opw,
                       const int* __restrict__ ei, const float* __restrict__ ea) {
    int b = blockIdx.x;
    if (b < TB0) {
        int idx = b * 256 + threadIdx.x;
        if (idx >= Nn * Ff * Tt) return;
        int f = idx & (Ff - 1);
        int t = (idx / Ff) % Tt;
        int n = idx / (Ff * Tt);
        g_xt[(size_t)t * Nn * Ff + (size_t)n * Ff + f] =
            x[(size_t)n * Ff * Tt + (size_t)f * Tt + t];
    } else if (b < TB0 + TB1) {
        int i = (b - TB0) * 256 + threadIdx.x;
        if (i < 192 * Hh) { int r = i / Hh, c = i % Hh; g_ipwT[c * 192 + r] = ipw[i]; }
        if (i < Hh * Hh)  { int r = i / Hh, c = i % Hh; g_opwT[c * Hh + r] = opw[i]; }
    } else {
        int e = (b - TB0 - TB1) * 256 + threadIdx.x;
        if (e >= Ee) return;
        int d = ei[Ee + e];
        atomicAdd(&g_deg[d], ea[2 * e + 1]);
        atomicAdd(&g_cnt[d], 1);
    }
}

// ---------------- fast scan (shuffle-based) + fused dinv ----------------------
__global__ __launch_bounds__(1024) void k_scan() {
    const int ELT = 20;
    int tid = threadIdx.x;
    int base = tid * ELT;
    int v[ELT];
    int sum = 0;
#pragma unroll
    for (int i = 0; i < ELT; i++) {
        int idx = base + i;
        v[i] = (idx < Nn) ? g_cnt[idx] : 0;
        sum += v[i];
    }
    int lane = tid & 31, wid = tid >> 5;
    int s = sum;
#pragma unroll
    for (int off = 1; off < 32; off <<= 1) {
        int t2 = __shfl_up_sync(0xffffffffu, s, off);
        if (lane >= off) s += t2;
    }
    __shared__ int wsum[32];
    if (lane == 31) wsum[wid] = s;
    __syncthreads();
    if (wid == 0) {
        int ws = wsum[lane];
#pragma unroll
        for (int off = 1; off < 32; off <<= 1) {
            int t2 = __shfl_up_sync(0xffffffffu, ws, off);
            if (lane >= off) ws += t2;
        }
        wsum[lane] = ws;
    }
    __syncthreads();
    int offset = ((wid > 0) ? wsum[wid - 1] : 0) + (s - sum);
    if (tid == 0) g_rowptr[0] = 0;
    int run = offset;
#pragma unroll
    for (int i = 0; i < ELT; i++) {
        run += v[i];
        int idx = base + i;
        if (idx < Nn) g_rowptr[idx + 1] = run;
    }
    for (int n = tid; n < Nn; n += 1024)
        g_dinv[n] = rsqrtf(g_deg[n] + 1.0f);
}

// fill + fused norm computation
__global__ void k_fill(const int* __restrict__ ei, const float* __restrict__ ea) {
    int e = blockIdx.x * blockDim.x + threadIdx.x;
    if (e >= Ee) return;
    int s = ei[e], d = ei[Ee + e];
    int pos = g_rowptr[d] + atomicAdd(&g_cur[d], 1);
    g_csrsrc[pos] = s;
    g_csrnorm[pos] = g_dinv[s] * ea[2 * e + 1] * g_dinv[d];
}

// ---------------- raw-feature GCN aggregate for all t (F=32) ------------------
__global__ void k_aggx_all() {
    int gw = blockIdx.x * (blockDim.x >> 5) + (threadIdx.x >> 5);
    if (gw >= TN) return;
    int t = gw / Nn, n = gw - t * Nn;
    int lane = threadIdx.x & 31;
    const float* xs = g_xt + (size_t)t * Nn * Ff;
    int beg = g_rowptr[n], end = g_rowptr[n + 1];
    float a0 = 0.f;
#pragma unroll 4
    for (int p = beg; p < end; p++) {
        int s = g_csrsrc[p];
        float nm = g_csrnorm[p];
        a0 += nm * xs[(size_t)s * Ff + lane];
    }
    float dv = g_dinv[n];
    a0 += dv * dv * xs[(size_t)n * Ff + lane];
    g_aggx[(size_t)gw * Ff + lane] = a0;
}

// ---------------- pre0 fused: g0 in-register, then p0 = [x|g0]@W + b ---------
__global__ __launch_bounds__(128, 3) void k_pre0m(const float* __restrict__ bg,
                                                  const float* __restrict__ bu,
                                                  const float* __restrict__ br,
                                                  const float* __restrict__ bc) {
    __shared__ unsigned U[64 * 72];
    int tid = threadIdx.x, lane = tid & 31, w = tid >> 5;
    int qr = lane >> 2, qc = lane & 3;
    int rl0 = w * 16 + qr;
    int r0 = blockIdx.x * 64 + rl0, r1 = r0 + 8;   // TN % 64 == 0, all valid
    // g0 = sigmoid(aggx @ Wg0 + bg) -> U (tf32, [col][row])
    {
        float Cg[8][4] = {};
        unsigned a[4][4];
        load_A_chunk(a, g_aggx, Ff, r0, r1, true, true, 0, qc);
        mma_gate(Cg, a, g_pkall + (size_t)PK_WG0 * 2048, lane);
#pragma unroll
        for (int f = 0; f < 8; f++) {
            int col = 8 * f + 2 * qc;
            float2 b2 = *(const float2*)(bg + col);
#pragma unroll
            for (int half = 0; half < 2; half++) {
                int rl = rl0 + 8 * half;
                U[col * 72 + rl] = f2tf32(sigmoidf_(Cg[f][2 * half + 0] + b2.x));
                U[(col + 1) * 72 + rl] = f2tf32(sigmoidf_(Cg[f][2 * half + 1] + b2.y));
            }
        }
    }
    __syncwarp();
    float C[3][8][4] = {};
    for (int ch = 0; ch < 3; ch++) {
        unsigned a[4][4];
        if (ch == 0) load_A_chunk(a, g_xt, Ff, r0, r1, true, true, 0, qc);
        else         load_A_smemU(a, U, rl0, (ch - 1) * 32, qc);
#pragma unroll
        for (int g = 0; g < 3; g++)
            mma_gate(C[g], a, g_pkall + (size_t)(PK_PRE0 + g * 3 + ch) * 2048, lane);
    }
#pragma unroll
    for (int g = 0; g < 3; g++) {
        const float* b = (g == 0) ? bu : (g == 1) ? br : bc;
#pragma unroll
        for (int f = 0; f < 8; f++) {
            int col = 8 * f + 2 * qc;
            float2 b2 = *(const float2*)(b + col);
            *(float2*)(g_p0all + (size_t)r0 * 192 + g * 64 + col) =
                make_float2(C[g][f][0] + b2.x, C[g][f][1] + b2.y);
            *(float2*)(g_p0all + (size_t)r1 * 192 + g * 64 + col) =
                make_float2(C[g][f][2] + b2.x, C[g][f][3] + b2.y);
        }
    }
}

// ---------------- per-step GCN agg (layer1, 1 warp/node, 0 smem) -------------
__global__ void k_gcn_agg(const float* __restrict__ bg) {
    int n = blockIdx.x * (blockDim.x >> 5) + (threadIdx.x >> 5);
    if (n >= Nn) return;
    int lane = threadIdx.x & 31;
    int beg = g_rowptr[n], end = g_rowptr[n + 1];
    float a0 = 0.f, a1 = 0.f;
#pragma unroll 4
    for (int p = beg; p < end; p++) {
        int s = g_csrsrc[p];
        float nm = g_csrnorm[p];
        a0 += nm * g_xw[(size_t)s * Hh + lane];
        a1 += nm * g_xw[(size_t)s * Hh + lane + 32];
    }
    float dv = g_dinv[n];
    float dd = dv * dv;
    a0 += dd * g_xw[(size_t)n * Hh + lane] + bg[lane];
    a1 += dd * g_xw[(size_t)n * Hh + lane + 32] + bg[lane + 32];
    g_gg[(size_t)n * Hh + lane] = sigmoidf_(a0);
    g_gg[(size_t)n * Hh + lane + 32] = sigmoidf_(a1);
}

// ---------------- layer0 urc + GRU update + xw=h@Wg1 (pipelined) -------------
__global__ __launch_bounds__(128, 3) void k_urc0x(const float* __restrict__ p0,
                                                  float* __restrict__ h,
                                                  float* __restrict__ xw) {
    __shared__ unsigned U[64 * 72];
    int tid = threadIdx.x, lane = tid & 31, w = tid >> 5;
    int qr = lane >> 2, qc = lane & 3;
    int rl0 = w * 16 + qr;
    int r0 = blockIdx.x * 64 + rl0, r1 = r0 + 8;
    bool v0 = r0 < Nn, v1 = r1 < Nn;
    float araw[16];
    load_A_raw(araw, h, 64, r0, r1, v0, v1, 0, qc);
    float Cu[8][4], Cr[8][4], Cc[8][4];
#pragma unroll
    for (int f = 0; f < 8; f++) {
        int col = 8 * f + 2 * qc;
        float2 z = make_float2(0.f, 0.f);
        float2 u0 = z, u1 = z, rr0 = z, rr1 = z, c0 = z, c1 = z;
        if (v0) {
            u0  = *(const float2*)(p0 + (size_t)r0 * 192 + col);
            rr0 = *(const float2*)(p0 + (size_t)r0 * 192 + 64 + col);
            c0  = *(const float2*)(p0 + (size_t)r0 * 192 + 128 + col);
        }
        if (v1) {
            u1  = *(const float2*)(p0 + (size_t)r1 * 192 + col);
            rr1 = *(const float2*)(p0 + (size_t)r1 * 192 + 64 + col);
            c1  = *(const float2*)(p0 + (size_t)r1 * 192 + 128 + col);
        }
        Cu[f][0] = u0.x;  Cu[f][1] = u0.y;  Cu[f][2] = u1.x;  Cu[f][3] = u1.y;
        Cr[f][0] = rr0.x; Cr[f][1] = rr0.y; Cr[f][2] = rr1.x; Cr[f][3] = rr1.y;
        Cc[f][0] = c0.x;  Cc[f][1] = c0.y;  Cc[f][2] = c1.x;  Cc[f][3] = c1.y;
    }
#pragma unroll
    for (int ch = 0; ch < 2; ch++) {
        unsigned a[4][4];
        cvt_frag(a, araw);
        if (ch == 0) load_A_raw(araw, h, 64, r0, r1, v0, v1, 32, qc);
        mma_gate(Cu, a, g_pkall + (size_t)(PK_URC0 + 0 + ch) * 2048, lane);
        mma_gate(Cr, a, g_pkall + (size_t)(PK_URC0 + 2 + ch) * 2048, lane);
    }
#pragma unroll
    for (int f = 0; f < 8; f++) {
        int col = 8 * f + 2 * qc;
#pragma unroll
        for (int half = 0; half < 2; half++) {
            int rl = rl0 + 8 * half;
            int row = blockIdx.x * 64 + rl;
            float u0 = sigmoidf_(Cu[f][2 * half + 0]);
            float u1 = sigmoidf_(Cu[f][2 * half + 1]);
            float rg0 = sigmoidf_(Cr[f][2 * half + 0]);
            float rg1 = sigmoidf_(Cr[f][2 * half + 1]);
            Cu[f][2 * half + 0] = u0;
            Cu[f][2 * half + 1] = u1;
            float2 hv = make_float2(0.f, 0.f);
            if (row < Nn) hv = *(const float2*)(h + (size_t)row * 64 + col);
            Cr[f][2 * half + 0] = hv.x;
            Cr[f][2 * half + 1] = hv.y;
            U[col * 72 + rl] = f2tf32(rg0 * hv.x);
            U[(col + 1) * 72 + rl] = f2tf32(rg1 * hv.y);
        }
    }
    __syncwarp();
    for (int ch = 0; ch < 2; ch++) {
        unsigned a[4][4];
        load_A_smemU(a, U, rl0, ch * 32, qc);
        mma_gate(Cc, a, g_pkall + (size_t)(PK_URC0 + 4 + ch) * 2048, lane);
    }
#pragma unroll
    for (int f = 0; f < 8; f++) {
        int col = 8 * f + 2 * qc;
#pragma unroll
        for (int half = 0; half < 2; half++) {
            int rl = rl0 + 8 * half;
            int row = blockIdx.x * 64 + rl;
            float hv0 = Cr[f][2 * half + 0], hv1 = Cr[f][2 * half + 1];
            float c0 = tanhf(Cc[f][2 * half + 0]);
            float c1 = tanhf(Cc[f][2 * half + 1]);
            float u0 = Cu[f][2 * half + 0], u1 = Cu[f][2 * half + 1];
            float o0 = u0 * hv0 + (1.f - u0) * c0;
            float o1 = u1 * hv1 + (1.f - u1) * c1;
            if (row < Nn) *(float2*)(h + (size_t)row * 64 + col) = make_float2(o0, o1);
            U[col * 72 + rl] = f2tf32(o0);
            U[(col + 1) * 72 + rl] = f2tf32(o1);
        }
    }
    __syncwarp();
    float Cx[8][4] = {};
    for (int ch = 0; ch < 2; ch++) {
        unsigned a[4][4];
        load_A_smemU(a, U, rl0, ch * 32, qc);
        mma_gate(Cx, a, g_pkall + (size_t)(PK_WG1 + ch) * 2048, lane);
    }
#pragma unroll
    for (int f = 0; f < 8; f++) {
        int col = 8 * f + 2 * qc;
        if (v0) *(float2*)(xw + (size_t)r0 * 64 + col) = make_float2(Cx[f][0], Cx[f][1]);
        if (v1) *(float2*)(xw + (size_t)r1 * 64 + col) = make_float2(Cx[f][2], Cx[f][3]);
    }
}

// ---------------- layer1 urc + GRU + fused qkv of this step ------------------
__global__ __launch_bounds__(128, 3) void k_urc1q(
    const float* __restrict__ h0,
    const float* __restrict__ bu, const float* __restrict__ br,
    const float* __restrict__ bc, const float* __restrict__ ipb,
    float* __restrict__ h, float* __restrict__ qkvt) {
    __shared__ unsigned U[64 * 72];
    int tid = threadIdx.x, lane = tid & 31, w = tid >> 5;
    int qr = lane >> 2, qc = lane & 3;
    int rl0 = w * 16 + qr;
    int r0 = blockIdx.x * 64 + rl0, r1 = r0 + 8;
    bool v0 = r0 < Nn, v1 = r1 < Nn;
    float Cu[8][4] = {}, Cr[8][4] = {}, Cc[8][4] = {};
    float araw[16];
    load_A_raw(araw, h0, 64, r0, r1, v0, v1, 0, qc);
#pragma unroll
    for (int ch = 0; ch < 6; ch++) {
        unsigned a[4][4];
        cvt_frag(a, araw);
        if (ch < 5) {
            int cn = ch + 1;
            const float* Sn = (cn < 2) ? h0 : (cn < 4) ? g_gg : h;
            load_A_raw(araw, Sn, 64, r0, r1, v0, v1, (cn & 1) * 32, qc);
        }
        mma_gate(Cu, a, g_pkall + (size_t)(PK_URC1 + ch) * 2048, lane);
        mma_gate(Cr, a, g_pkall + (size_t)(PK_URC1 + 6 + ch) * 2048, lane);
        if (ch < 4) mma_gate(Cc, a, g_pkall + (size_t)(PK_URC1 + 12 + ch) * 2048, lane);
    }
#pragma unroll
    for (int f = 0; f < 8; f++) {
        int col = 8 * f + 2 * qc;
        float2 bu2 = *(const float2*)(bu + col);
        float2 br2 = *(const float2*)(br + col);
#pragma unroll
        for (int half = 0; half < 2; half++) {
            int rl = rl0 + 8 * half;
            int row = blockIdx.x * 64 + rl;
            float u0 = sigmoidf_(Cu[f][2 * half + 0] + bu2.x);
            float u1 = sigmoidf_(Cu[f][2 * half + 1] + bu2.y);
            float rg0 = sigmoidf_(Cr[f][2 * half + 0] + br2.x);
            float rg1 = sigmoidf_(Cr[f][2 * half + 1] + br2.y);
            Cu[f][2 * half + 0] = u0;
            Cu[f][2 * half + 1] = u1;
            float2 hv = make_float2(0.f, 0.f);
            if (row < Nn) hv = *(const float2*)(h + (size_t)row * 64 + col);
            Cr[f][2 * half + 0] = hv.x;
            Cr[f][2 * half + 1] = hv.y;
            U[col * 72 + rl] = f2tf32(rg0 * hv.x);
            U[(col + 1) * 72 + rl] = f2tf32(rg1 * hv.y);
        }
    }
    __syncwarp();
    for (int ch = 0; ch < 2; ch++) {
        unsigned a[4][4];
        load_A_smemU(a, U, rl0, ch * 32, qc);
        mma_gate(Cc, a, g_pkall + (size_t)(PK_URC1 + 16 + ch) * 2048, lane);
    }
    // epilogue2: h_new -> h, and restage h_new into U for the qkv pass
#pragma unroll
    for (int f = 0; f < 8; f++) {
        int col = 8 * f + 2 * qc;
        float2 bc2 = *(const float2*)(bc + col);
#pragma unroll
        for (int half = 0; half < 2; half++) {
            int rl = rl0 + 8 * half;
            int row = blockIdx.x * 64 + rl;
            float hv0 = Cr[f][2 * half + 0], hv1 = Cr[f][2 * half + 1];
            float c0 = tanhf(Cc[f][2 * half + 0] + bc2.x);
            float c1 = tanhf(Cc[f][2 * half + 1] + bc2.y);
            float u0 = Cu[f][2 * half + 0], u1 = Cu[f][2 * half + 1];
            float o0 = u0 * hv0 + (1.f - u0) * c0;
            float o1 = u1 * hv1 + (1.f - u1) * c1;
            if (row < Nn) *(float2*)(h + (size_t)row * 64 + col) = make_float2(o0, o1);
            U[col * 72 + rl] = f2tf32(o0);
            U[(col + 1) * 72 + rl] = f2tf32(o1);
        }
    }
    __syncwarp();
    // qkv_t = h1 @ ipw^T + ipb  (3 gates sequentially; reuses one accumulator)
#pragma unroll
    for (int g = 0; g < 3; g++) {
        float Cq[8][4] = {};
        for (int ch = 0; ch < 2; ch++) {
            unsigned a[4][4];
            load_A_smemU(a, U, rl0, ch * 32, qc);
            mma_gate(Cq, a, g_pkall + (size_t)(PK_QKV + g * 2 + ch) * 2048, lane);
        }
#pragma unroll
        for (int f = 0; f < 8; f++) {
            int col = 8 * f + 2 * qc;
            float2 b2 = *(const float2*)(ipb + g * 64 + col);
            if (v0) *(float2*)(qkvt + (size_t)r0 * 192 + g * 64 + col) =
                make_float2(Cq[f][0] + b2.x, Cq[f][1] + b2.y);
            if (v1) *(float2*)(qkvt + (size_t)r1 * 192 + g * 64 + col) =
                make_float2(Cq[f][2] + b2.x, Cq[f][3] + b2.y);
        }
    }
}

// ---------------- attention tail -------------------------------------------
__global__ __launch_bounds__(128) void k_attn2(
    const float* __restrict__ opb,
    const float* __restrict__ ow, const float* __restrict__ ob,
    float* __restrict__ out) {
    __shared__ float s_qkv[4][Tt * 192];
    __shared__ float s_sc[4][2 * Tt * Tt];
    __shared__ float s_cs[4][2 * Tt];
    __shared__ float s_ob[4][Hh];
    __shared__ float s_ha[4][Hh];
    int w = threadIdx.x >> 5, lane = threadIdx.x & 31;
    int n = blockIdx.x * 4 + w;
    if (n >= Nn) return;
    float* qkv = s_qkv[w];
    float* sc = s_sc[w];
    float* cs = s_cs[w];
    float* obw = s_ob[w];
    float* haw = s_ha[w];

    for (int i = lane; i < Tt * 48; i += 32) {
        int t = i / 48, r = i % 48;
        *(float4*)&qkv[t * 192 + r * 4] =
            *(const float4*)&g_qkv[((size_t)t * Nn + n) * 192 + r * 4];
    }
    __syncwarp();
    for (int idx = lane; idx < 2 * Tt * Tt; idx += 32) {
        int hd = idx / (Tt * Tt);
        int r = idx % (Tt * Tt);
        int t = r / Tt, s = r % Tt;
        const float* qp = &qkv[t * 192 + hd * 32];
        const float* kp = &qkv[s * 192 + 64 + hd * 32];
        float a = 0.f;
#pragma unroll
        for (int d = 0; d < 32; d++) a += qp[d] * kp[d];
        sc[idx] = a * 0.17677669529663687f;
    }
    __syncwarp();
    if (lane < 2 * Tt) {
        float* row = &sc[lane * Tt];
        float mx = row[0];
#pragma unroll
        for (int s = 1; s < Tt; s++) mx = fmaxf(mx, row[s]);
        float sum = 0.f;
#pragma unroll
        for (int s = 0; s < Tt; s++) { float e = __expf(row[s] - mx); row[s] = e; sum += e; }
        float inv = 1.0f / sum;
#pragma unroll
        for (int s = 0; s < Tt; s++) row[s] *= inv;
    }
    __syncwarp();
    if (lane < 2 * Tt) {
        int hd = lane / Tt, s = lane % Tt;
        float a = 0.f;
#pragma unroll
        for (int t = 0; t < Tt; t++) a += sc[hd * Tt * Tt + t * Tt + s];
        cs[lane] = a * (1.0f / 12.0f);
    }
    __syncwarp();
    for (int m = 0; m < 2; m++) {
        int j = lane + 32 * m;
        int hd = j >> 5;
        float a = 0.f;
#pragma unroll
        for (int s = 0; s < Tt; s++) a += cs[hd * Tt + s] * qkv[s * 192 + 128 + j];
        obw[j] = a;
    }
    __syncwarp();
    for (int m = 0; m < 2; m++) {
        int i = lane + 32 * m;
        float a = opb[i];
#pragma unroll
        for (int j = 0; j < Hh; j++) a += g_opwT[j * Hh + i] * obw[j];
        haw[i] = a;
    }
    __syncwarp();
    if (lane < OUTD) {
        float a = ob[lane];
#pragma unroll
        for (int i = 0; i < Hh; i++) a += haw[i] * ow[(size_t)i * OUTD + lane];
        out[(size_t)n * OUTD + lane] = a;
    }
}

// ---------------- host ----------------
extern "C" void kernel_launch(void* const* d_in, const int* in_sizes, int n_in,
                              void* d_out, int out_size) {
    (void)in_sizes; (void)n_in; (void)out_size;
    const float* x   = (const float*)d_in[0];
    const int*   ei  = (const int*)d_in[1];
    const float* ea  = (const float*)d_in[2];
    const float* Wg0 = (const float*)d_in[3];
    const float* bg0 = (const float*)d_in[4];
    const float* Wu0 = (const float*)d_in[5];
    const float* bu0 = (const float*)d_in[6];
    const float* Wr0 = (const float*)d_in[7];
    const float* br0 = (const float*)d_in[8];
    const float* Wc0 = (const float*)d_in[9];
    const float* bc0 = (const float*)d_in[10];
    const float* Wg1 = (const float*)d_in[11];
    const float* bg1 = (const float*)d_in[12];
    const float* Wu1 = (const float*)d_in[13];
    const float* bu1 = (const float*)d_in[14];
    const float* Wr1 = (const float*)d_in[15];
    const float* br1 = (const float*)d_in[16];
    const float* Wc1 = (const float*)d_in[17];
    const float* bc1 = (const float*)d_in[18];
    const float* ipw = (const float*)d_in[19];
    const float* ipb = (const float*)d_in[20];
    const float* opw = (const float*)d_in[21];
    const float* opb = (const float*)d_in[22];
    const float* ow  = (const float*)d_in[23];
    const float* ob  = (const float*)d_in[24];
    float* out = (float*)d_out;

    void *p_deg, *p_cnt, *p_cur, *p_h0, *p_h1, *p_qkv;
    void *p_p0all, *p_xw, *p_ipwT;
    cudaGetSymbolAddress(&p_deg, g_deg);
    cudaGetSymbolAddress(&p_cnt, g_cnt);
    cudaGetSymbolAddress(&p_cur, g_cur);
    cudaGetSymbolAddress(&p_h0, g_h0);
    cudaGetSymbolAddress(&p_h1, g_h1);
    cudaGetSymbolAddress(&p_qkv, g_qkv);
    cudaGetSymbolAddress(&p_p0all, g_p0all);
    cudaGetSymbolAddress(&p_xw, g_xw);
    cudaGetSymbolAddress(&p_ipwT, g_ipwT);

    cudaMemsetAsync(p_deg, 0, Nn * sizeof(float), 0);
    cudaMemsetAsync(p_cnt, 0, Nn * sizeof(int), 0);
    cudaMemsetAsync(p_cur, 0, Nn * sizeof(int), 0);
    cudaMemsetAsync(p_h0, 0, (size_t)Nn * Hh * sizeof(float), 0);
    cudaMemsetAsync(p_h1, 0, (size_t)Nn * Hh * sizeof(float), 0);

    k_prep<<<TB0 + TB1 + TB2, 256>>>(x, ipw, opw, ei, ea);
    k_scan<<<1, 1024>>>();
    k_fill<<<(Ee + 255) / 256, 256>>>(ei, ea);

    // ---- single-launch weight packing ----
    float* ipwT = (float*)p_ipwT;
    PackTab tab;
    int gi = 0;
    tab.src[gi] = Wg0; tab.ldw[gi++] = 64;
    const float* Ws0[3] = {Wu0, Wr0, Wc0};
    for (int g = 0; g < 3; g++)
        for (int c = 0; c < 3; c++) { tab.src[gi] = Ws0[g] + (size_t)c * 32 * 64; tab.ldw[gi++] = 64; }
    for (int g = 0; g < 3; g++)
        for (int c = 0; c < 2; c++) { tab.src[gi] = Ws0[g] + (size_t)(96 + c * 32) * 64; tab.ldw[gi++] = 64; }
    for (int c = 0; c < 2; c++) { tab.src[gi] = Wg1 + (size_t)c * 32 * 64; tab.ldw[gi++] = 64; }
    const float* Ws1[3] = {Wu1, Wr1, Wc1};
    for (int g = 0; g < 3; g++)
        for (int c = 0; c < 6; c++) { tab.src[gi] = Ws1[g] + (size_t)c * 32 * 64; tab.ldw[gi++] = 64; }
    for (int g = 0; g < 3; g++)
        for (int c = 0; c < 2; c++) { tab.src[gi] = ipwT + g * 64 + (size_t)c * 32 * 192; tab.ldw[gi++] = 192; }
    k_packall<<<(42 * 512 + 255) / 256, 256>>>(tab);

    // ---- hoisted precomputes ----
    k_aggx_all<<<(TN + 7) / 8, 256>>>();
    k_pre0m<<<TN / 64, 128>>>(bg0, bu0, br0, bc0);

    const int AGG_GRID = (Nn + 7) / 8;
    float* h0 = (float*)p_h0;
    float* h1 = (float*)p_h1;
    float* xw = (float*)p_xw;
    const float* p0all = (const float*)p_p0all;
    float* qkv = (float*)p_qkv;

    for (int t = 0; t < Tt; t++) {
        k_urc0x<<<GB, 128>>>(p0all + (size_t)t * Nn * 192, h0, xw);
        k_gcn_agg<<<AGG_GRID, 256>>>(bg1);
        k_urc1q<<<GB, 128>>>(h0, bu1, br1, bc1, ipb, h1,
                             qkv + (size_t)t * Nn * 192);
    }

    k_attn2<<<(Nn + 3) / 4, 128>>>(opb, ow, ob, out);
}

// round 17
// speedup vs baseline: 1.1083x; 1.0449x over previous
#include <cuda_runtime.h>
#include <math.h>
#include <stdint.h>

#define Nn 20000
#define Ff 32
#define Tt 12
#define Hh 64
#define Ee 320000
#define OUTD 12
#define TN (Tt * Nn)
#define GB 313

// ---------------- scratch ----------------
static __device__ float g_xt[(size_t)TN * Ff];
static __device__ float g_deg[Nn];
static __device__ float g_dinv[Nn];
static __device__ int   g_cnt[Nn];
static __device__ int   g_cur[Nn];
static __device__ int   g_rowptr[Nn + 1];
static __device__ int   g_csrsrc[Ee];
static __device__ float g_csrnorm[Ee];
static __device__ float g_aggx[(size_t)TN * Ff];
static __device__ float g_p0all[(size_t)TN * 192];
static __device__ float g_xwA[(size_t)Nn * Hh];      // xw ping-pong
static __device__ float g_xwB[(size_t)Nn * Hh];
static __device__ float g_gg[(size_t)Nn * Hh];
static __device__ float g_h0a[(size_t)Nn * Hh];      // h0 ping-pong
static __device__ float g_h0b[(size_t)Nn * Hh];
static __device__ float g_h1[(size_t)Nn * Hh];
static __device__ float g_qkv[(size_t)TN * 192];
static __device__ float g_ipwT[Hh * 192];
static __device__ float g_opwT[Hh * Hh];

// unified pre-packed tf32 b-fragments: 42 chunks x 2048 unsigned
static __device__ unsigned g_pkall[42 * 2048];
#define PK_WG0  0
#define PK_PRE0 1
#define PK_URC0 10
#define PK_WG1  16
#define PK_URC1 18
#define PK_QKV  36

struct PackTab { const float* src[42]; int ldw[42]; };

__device__ __forceinline__ float sigmoidf_(float x) { return 1.0f / (1.0f + __expf(-x)); }

__device__ __forceinline__ unsigned f2tf32(float f) {
    unsigned r;
    asm("cvt.rna.tf32.f32 %0, %1;" : "=r"(r) : "f"(f));
    return r;
}

__device__ __forceinline__ void mma_tf32(float c[4], const unsigned a[4], unsigned b0, unsigned b1) {
    asm volatile(
        "mma.sync.aligned.m16n8k8.row.col.f32.tf32.tf32.f32 "
        "{%0,%1,%2,%3}, {%4,%5,%6,%7}, {%8,%9}, {%0,%1,%2,%3};"
        : "+f"(c[0]), "+f"(c[1]), "+f"(c[2]), "+f"(c[3])
        : "r"(a[0]), "r"(a[1]), "r"(a[2]), "r"(a[3]), "r"(b0), "r"(b1));
}

__device__ __forceinline__ void load_A_raw(float x[16], const float* __restrict__ A,
                                           int lda, int r0, int r1, bool v0, bool v1,
                                           int k0, int qc) {
#pragma unroll
    for (int s = 0; s < 4; s++) {
        int k = k0 + 8 * s + qc;
        x[4 * s + 0] = v0 ? A[(size_t)r0 * lda + k] : 0.f;
        x[4 * s + 1] = v1 ? A[(size_t)r1 * lda + k] : 0.f;
        x[4 * s + 2] = v0 ? A[(size_t)r0 * lda + k + 4] : 0.f;
        x[4 * s + 3] = v1 ? A[(size_t)r1 * lda + k + 4] : 0.f;
    }
}

__device__ __forceinline__ void cvt_frag(unsigned a[4][4], const float x[16]) {
#pragma unroll
    for (int s = 0; s < 4; s++)
#pragma unroll
        for (int j = 0; j < 4; j++) a[s][j] = f2tf32(x[4 * s + j]);
}

__device__ __forceinline__ void load_A_chunk(unsigned a[4][4], const float* __restrict__ A,
                                             int lda, int r0, int r1, bool v0, bool v1,
                                             int k0, int qc) {
    float x[16];
    load_A_raw(x, A, lda, r0, r1, v0, v1, k0, qc);
    cvt_frag(a, x);
}

__device__ __forceinline__ void load_A_smemU(unsigned a[4][4], const unsigned* U,
                                             int rl0, int k0, int qc) {
#pragma unroll
    for (int s = 0; s < 4; s++) {
        int k = k0 + 8 * s + qc;
        a[s][0] = U[k * 72 + rl0];
        a[s][1] = U[k * 72 + rl0 + 8];
        a[s][2] = U[(k + 4) * 72 + rl0];
        a[s][3] = U[(k + 4) * 72 + rl0 + 8];
    }
}

__device__ __forceinline__ void mma_gate(float C[8][4], const unsigned a[4][4],
                                         const unsigned* __restrict__ Bpk, int lane) {
    const uint4* B4 = (const uint4*)Bpk;
#pragma unroll
    for (int s = 0; s < 4; s++)
#pragma unroll
        for (int f2 = 0; f2 < 4; f2++) {
            uint4 b = B4[(s * 4 + f2) * 32 + lane];
            mma_tf32(C[2 * f2], a[s], b.x, b.y);
            mma_tf32(C[2 * f2 + 1], a[s], b.z, b.w);
        }
}

// ---------------- single-launch weight pack ----------------------------------
__global__ void k_packall(PackTab tab) {
    int tid = blockIdx.x * blockDim.x + threadIdx.x;
    if (tid >= 42 * 512) return;
    int g = tid >> 9, r = tid & 511;
    const float* W = tab.src[g];
    int ldw = tab.ldw[g];
    int s = r >> 7, f2 = (r >> 5) & 3, lane = r & 31;
    int qr = lane >> 2, qc = lane & 3;
    int k1 = 8 * s + qc, k2 = k1 + 4;
    int n1 = 16 * f2 + qr, n2 = n1 + 8;
    uint4 o;
    o.x = f2tf32(W[(size_t)k1 * ldw + n1]);
    o.y = f2tf32(W[(size_t)k2 * ldw + n1]);
    o.z = f2tf32(W[(size_t)k1 * ldw + n2]);
    o.w = f2tf32(W[(size_t)k2 * ldw + n2]);
    ((uint4*)g_pkall)[tid] = o;
}

// ---------------- merged elementwise preproc ---------------------------------
#define TB0 ((Nn * Ff * Tt + 255) / 256)
#define TB1 48
#define TB2 ((Ee + 255) / 256)
__global__ void k_prep(const float* __restrict__ x,
                       const float* __restrict__ ipw, const float* __restrict__ opw,
                       const int* __restrict__ ei, const float* __restrict__ ea) {
    int b = blockIdx.x;
    if (b < TB0) {
        int idx = b * 256 + threadIdx.x;
        if (idx >= Nn * Ff * Tt) return;
        int f = idx & (Ff - 1);
        int t = (idx / Ff) % Tt;
        int n = idx / (Ff * Tt);
        g_xt[(size_t)t * Nn * Ff + (size_t)n * Ff + f] =
            x[(size_t)n * Ff * Tt + (size_t)f * Tt + t];
    } else if (b < TB0 + TB1) {
        int i = (b - TB0) * 256 + threadIdx.x;
        if (i < 192 * Hh) { int r = i / Hh, c = i % Hh; g_ipwT[c * 192 + r] = ipw[i]; }
        if (i < Hh * Hh)  { int r = i / Hh, c = i % Hh; g_opwT[c * Hh + r] = opw[i]; }
    } else {
        int e = (b - TB0 - TB1) * 256 + threadIdx.x;
        if (e >= Ee) return;
        int d = ei[Ee + e];
        atomicAdd(&g_deg[d], ea[2 * e + 1]);
        atomicAdd(&g_cnt[d], 1);
    }
}

// ---------------- fast scan + fused dinv --------------------------------------
__global__ __launch_bounds__(1024) void k_scan() {
    const int ELT = 20;
    int tid = threadIdx.x;
    int base = tid * ELT;
    int v[ELT];
    int sum = 0;
#pragma unroll
    for (int i = 0; i < ELT; i++) {
        int idx = base + i;
        v[i] = (idx < Nn) ? g_cnt[idx] : 0;
        sum += v[i];
    }
    int lane = tid & 31, wid = tid >> 5;
    int s = sum;
#pragma unroll
    for (int off = 1; off < 32; off <<= 1) {
        int t2 = __shfl_up_sync(0xffffffffu, s, off);
        if (lane >= off) s += t2;
    }
    __shared__ int wsum[32];
    if (lane == 31) wsum[wid] = s;
    __syncthreads();
    if (wid == 0) {
        int ws = wsum[lane];
#pragma unroll
        for (int off = 1; off < 32; off <<= 1) {
            int t2 = __shfl_up_sync(0xffffffffu, ws, off);
            if (lane >= off) ws += t2;
        }
        wsum[lane] = ws;
    }
    __syncthreads();
    int offset = ((wid > 0) ? wsum[wid - 1] : 0) + (s - sum);
    if (tid == 0) g_rowptr[0] = 0;
    int run = offset;
#pragma unroll
    for (int i = 0; i < ELT; i++) {
        run += v[i];
        int idx = base + i;
        if (idx < Nn) g_rowptr[idx + 1] = run;
    }
    for (int n = tid; n < Nn; n += 1024)
        g_dinv[n] = rsqrtf(g_deg[n] + 1.0f);
}

// fill + fused norm
__global__ void k_fill(const int* __restrict__ ei, const float* __restrict__ ea) {
    int e = blockIdx.x * blockDim.x + threadIdx.x;
    if (e >= Ee) return;
    int s = ei[e], d = ei[Ee + e];
    int pos = g_rowptr[d] + atomicAdd(&g_cur[d], 1);
    g_csrsrc[pos] = s;
    g_csrnorm[pos] = g_dinv[s] * ea[2 * e + 1] * g_dinv[d];
}

// ---------------- raw-feature GCN aggregate for all t -------------------------
__global__ void k_aggx_all() {
    int gw = blockIdx.x * (blockDim.x >> 5) + (threadIdx.x >> 5);
    if (gw >= TN) return;
    int t = gw / Nn, n = gw - t * Nn;
    int lane = threadIdx.x & 31;
    const float* xs = g_xt + (size_t)t * Nn * Ff;
    int beg = g_rowptr[n], end = g_rowptr[n + 1];
    float a0 = 0.f;
#pragma unroll 4
    for (int p = beg; p < end; p++) {
        int s = g_csrsrc[p];
        float nm = g_csrnorm[p];
        a0 += nm * xs[(size_t)s * Ff + lane];
    }
    float dv = g_dinv[n];
    a0 += dv * dv * xs[(size_t)n * Ff + lane];
    g_aggx[(size_t)gw * Ff + lane] = a0;
}

// ---------------- pre0 fused: g0 in-register, then p0 = [x|g0]@W + b ---------
__global__ __launch_bounds__(128, 3) void k_pre0m(const float* __restrict__ bg,
                                                  const float* __restrict__ bu,
                                                  const float* __restrict__ br,
                                                  const float* __restrict__ bc) {
    __shared__ unsigned U[64 * 72];
    int tid = threadIdx.x, lane = tid & 31, w = tid >> 5;
    int qr = lane >> 2, qc = lane & 3;
    int rl0 = w * 16 + qr;
    int r0 = blockIdx.x * 64 + rl0, r1 = r0 + 8;
    {
        float Cg[8][4] = {};
        unsigned a[4][4];
        load_A_chunk(a, g_aggx, Ff, r0, r1, true, true, 0, qc);
        mma_gate(Cg, a, g_pkall + (size_t)PK_WG0 * 2048, lane);
#pragma unroll
        for (int f = 0; f < 8; f++) {
            int col = 8 * f + 2 * qc;
            float2 b2 = *(const float2*)(bg + col);
#pragma unroll
            for (int half = 0; half < 2; half++) {
                int rl = rl0 + 8 * half;
                U[col * 72 + rl] = f2tf32(sigmoidf_(Cg[f][2 * half + 0] + b2.x));
                U[(col + 1) * 72 + rl] = f2tf32(sigmoidf_(Cg[f][2 * half + 1] + b2.y));
            }
        }
    }
    __syncwarp();
    float C[3][8][4] = {};
    for (int ch = 0; ch < 3; ch++) {
        unsigned a[4][4];
        if (ch == 0) load_A_chunk(a, g_xt, Ff, r0, r1, true, true, 0, qc);
        else         load_A_smemU(a, U, rl0, (ch - 1) * 32, qc);
#pragma unroll
        for (int g = 0; g < 3; g++)
            mma_gate(C[g], a, g_pkall + (size_t)(PK_PRE0 + g * 3 + ch) * 2048, lane);
    }
#pragma unroll
    for (int g = 0; g < 3; g++) {
        const float* b = (g == 0) ? bu : (g == 1) ? br : bc;
#pragma unroll
        for (int f = 0; f < 8; f++) {
            int col = 8 * f + 2 * qc;
            float2 b2 = *(const float2*)(b + col);
            *(float2*)(g_p0all + (size_t)r0 * 192 + g * 64 + col) =
                make_float2(C[g][f][0] + b2.x, C[g][f][1] + b2.y);
            *(float2*)(g_p0all + (size_t)r1 * 192 + g * 64 + col) =
                make_float2(C[g][f][2] + b2.x, C[g][f][3] + b2.y);
        }
    }
}

// ---------------- per-step GCN agg (xw param, 0 smem) -------------------------
__global__ void k_gcn_agg(const float* __restrict__ bg, const float* __restrict__ xw) {
    int n = blockIdx.x * (blockDim.x >> 5) + (threadIdx.x >> 5);
    if (n >= Nn) return;
    int lane = threadIdx.x & 31;
    int beg = g_rowptr[n], end = g_rowptr[n + 1];
    float a0 = 0.f, a1 = 0.f;
#pragma unroll 4
    for (int p = beg; p < end; p++) {
        int s = g_csrsrc[p];
        float nm = g_csrnorm[p];
        a0 += nm * xw[(size_t)s * Hh + lane];
        a1 += nm * xw[(size_t)s * Hh + lane + 32];
    }
    float dv = g_dinv[n];
    float dd = dv * dv;
    a0 += dd * xw[(size_t)n * Hh + lane] + bg[lane];
    a1 += dd * xw[(size_t)n * Hh + lane + 32] + bg[lane + 32];
    g_gg[(size_t)n * Hh + lane] = sigmoidf_(a0);
    g_gg[(size_t)n * Hh + lane + 32] = sigmoidf_(a1);
}

// ---------------- layer0 urc + GRU + xw=h@Wg1 (ping-pong h0) ------------------
__global__ __launch_bounds__(128, 3) void k_urc0x(const float* __restrict__ p0,
                                                  const float* __restrict__ h0r,
                                                  float* __restrict__ h0w,
                                                  float* __restrict__ xw) {
    __shared__ unsigned U[64 * 72];
    int tid = threadIdx.x, lane = tid & 31, w = tid >> 5;
    int qr = lane >> 2, qc = lane & 3;
    int rl0 = w * 16 + qr;
    int r0 = blockIdx.x * 64 + rl0, r1 = r0 + 8;
    bool v0 = r0 < Nn, v1 = r1 < Nn;
    float araw[16];
    load_A_raw(araw, h0r, 64, r0, r1, v0, v1, 0, qc);
    float Cu[8][4], Cr[8][4], Cc[8][4];
#pragma unroll
    for (int f = 0; f < 8; f++) {
        int col = 8 * f + 2 * qc;
        float2 z = make_float2(0.f, 0.f);
        float2 u0 = z, u1 = z, rr0 = z, rr1 = z, c0 = z, c1 = z;
        if (v0) {
            u0  = *(const float2*)(p0 + (size_t)r0 * 192 + col);
            rr0 = *(const float2*)(p0 + (size_t)r0 * 192 + 64 + col);
            c0  = *(const float2*)(p0 + (size_t)r0 * 192 + 128 + col);
        }
        if (v1) {
            u1  = *(const float2*)(p0 + (size_t)r1 * 192 + col);
            rr1 = *(const float2*)(p0 + (size_t)r1 * 192 + 64 + col);
            c1  = *(const float2*)(p0 + (size_t)r1 * 192 + 128 + col);
        }
        Cu[f][0] = u0.x;  Cu[f][1] = u0.y;  Cu[f][2] = u1.x;  Cu[f][3] = u1.y;
        Cr[f][0] = rr0.x; Cr[f][1] = rr0.y; Cr[f][2] = rr1.x; Cr[f][3] = rr1.y;
        Cc[f][0] = c0.x;  Cc[f][1] = c0.y;  Cc[f][2] = c1.x;  Cc[f][3] = c1.y;
    }
#pragma unroll
    for (int ch = 0; ch < 2; ch++) {
        unsigned a[4][4];
        cvt_frag(a, araw);
        if (ch == 0) load_A_raw(araw, h0r, 64, r0, r1, v0, v1, 32, qc);
        mma_gate(Cu, a, g_pkall + (size_t)(PK_URC0 + 0 + ch) * 2048, lane);
        mma_gate(Cr, a, g_pkall + (size_t)(PK_URC0 + 2 + ch) * 2048, lane);
    }
#pragma unroll
    for (int f = 0; f < 8; f++) {
        int col = 8 * f + 2 * qc;
#pragma unroll
        for (int half = 0; half < 2; half++) {
            int rl = rl0 + 8 * half;
            int row = blockIdx.x * 64 + rl;
            float u0 = sigmoidf_(Cu[f][2 * half + 0]);
            float u1 = sigmoidf_(Cu[f][2 * half + 1]);
            float rg0 = sigmoidf_(Cr[f][2 * half + 0]);
            float rg1 = sigmoidf_(Cr[f][2 * half + 1]);
            Cu[f][2 * half + 0] = u0;
            Cu[f][2 * half + 1] = u1;
            float2 hv = make_float2(0.f, 0.f);
            if (row < Nn) hv = *(const float2*)(h0r + (size_t)row * 64 + col);
            Cr[f][2 * half + 0] = hv.x;
            Cr[f][2 * half + 1] = hv.y;
            U[col * 72 + rl] = f2tf32(rg0 * hv.x);
            U[(col + 1) * 72 + rl] = f2tf32(rg1 * hv.y);
        }
    }
    __syncwarp();
    for (int ch = 0; ch < 2; ch++) {
        unsigned a[4][4];
        load_A_smemU(a, U, rl0, ch * 32, qc);
        mma_gate(Cc, a, g_pkall + (size_t)(PK_URC0 + 4 + ch) * 2048, lane);
    }
#pragma unroll
    for (int f = 0; f < 8; f++) {
        int col = 8 * f + 2 * qc;
#pragma unroll
        for (int half = 0; half < 2; half++) {
            int rl = rl0 + 8 * half;
            int row = blockIdx.x * 64 + rl;
            float hv0 = Cr[f][2 * half + 0], hv1 = Cr[f][2 * half + 1];
            float c0 = tanhf(Cc[f][2 * half + 0]);
            float c1 = tanhf(Cc[f][2 * half + 1]);
            float u0 = Cu[f][2 * half + 0], u1 = Cu[f][2 * half + 1];
            float o0 = u0 * hv0 + (1.f - u0) * c0;
            float o1 = u1 * hv1 + (1.f - u1) * c1;
            if (row < Nn) *(float2*)(h0w + (size_t)row * 64 + col) = make_float2(o0, o1);
            U[col * 72 + rl] = f2tf32(o0);
            U[(col + 1) * 72 + rl] = f2tf32(o1);
        }
    }
    __syncwarp();
    float Cx[8][4] = {};
    for (int ch = 0; ch < 2; ch++) {
        unsigned a[4][4];
        load_A_smemU(a, U, rl0, ch * 32, qc);
        mma_gate(Cx, a, g_pkall + (size_t)(PK_WG1 + ch) * 2048, lane);
    }
#pragma unroll
    for (int f = 0; f < 8; f++) {
        int col = 8 * f + 2 * qc;
        if (v0) *(float2*)(xw + (size_t)r0 * 64 + col) = make_float2(Cx[f][0], Cx[f][1]);
        if (v1) *(float2*)(xw + (size_t)r1 * 64 + col) = make_float2(Cx[f][2], Cx[f][3]);
    }
}

// ---------------- layer1 urc + GRU + fused qkv --------------------------------
__global__ __launch_bounds__(128, 3) void k_urc1q(
    const float* __restrict__ h0,
    const float* __restrict__ bu, const float* __restrict__ br,
    const float* __restrict__ bc, const float* __restrict__ ipb,
    float* __restrict__ h, float* __restrict__ qkvt) {
    __shared__ unsigned U[64 * 72];
    int tid = threadIdx.x, lane = tid & 31, w = tid >> 5;
    int qr = lane >> 2, qc = lane & 3;
    int rl0 = w * 16 + qr;
    int r0 = blockIdx.x * 64 + rl0, r1 = r0 + 8;
    bool v0 = r0 < Nn, v1 = r1 < Nn;
    float Cu[8][4] = {}, Cr[8][4] = {}, Cc[8][4] = {};
    float araw[16];
    load_A_raw(araw, h0, 64, r0, r1, v0, v1, 0, qc);
#pragma unroll
    for (int ch = 0; ch < 6; ch++) {
        unsigned a[4][4];
        cvt_frag(a, araw);
        if (ch < 5) {
            int cn = ch + 1;
            const float* Sn = (cn < 2) ? h0 : (cn < 4) ? g_gg : h;
            load_A_raw(araw, Sn, 64, r0, r1, v0, v1, (cn & 1) * 32, qc);
        }
        mma_gate(Cu, a, g_pkall + (size_t)(PK_URC1 + ch) * 2048, lane);
        mma_gate(Cr, a, g_pkall + (size_t)(PK_URC1 + 6 + ch) * 2048, lane);
        if (ch < 4) mma_gate(Cc, a, g_pkall + (size_t)(PK_URC1 + 12 + ch) * 2048, lane);
    }
#pragma unroll
    for (int f = 0; f < 8; f++) {
        int col = 8 * f + 2 * qc;
        float2 bu2 = *(const float2*)(bu + col);
        float2 br2 = *(const float2*)(br + col);
#pragma unroll
        for (int half = 0; half < 2; half++) {
            int rl = rl0 + 8 * half;
            int row = blockIdx.x * 64 + rl;
            float u0 = sigmoidf_(Cu[f][2 * half + 0] + bu2.x);
            float u1 = sigmoidf_(Cu[f][2 * half + 1] + bu2.y);
            float rg0 = sigmoidf_(Cr[f][2 * half + 0] + br2.x);
            float rg1 = sigmoidf_(Cr[f][2 * half + 1] + br2.y);
            Cu[f][2 * half + 0] = u0;
            Cu[f][2 * half + 1] = u1;
            float2 hv = make_float2(0.f, 0.f);
            if (row < Nn) hv = *(const float2*)(h + (size_t)row * 64 + col);
            Cr[f][2 * half + 0] = hv.x;
            Cr[f][2 * half + 1] = hv.y;
            U[col * 72 + rl] = f2tf32(rg0 * hv.x);
            U[(col + 1) * 72 + rl] = f2tf32(rg1 * hv.y);
        }
    }
    __syncwarp();
    for (int ch = 0; ch < 2; ch++) {
        unsigned a[4][4];
        load_A_smemU(a, U, rl0, ch * 32, qc);
        mma_gate(Cc, a, g_pkall + (size_t)(PK_URC1 + 16 + ch) * 2048, lane);
    }
#pragma unroll
    for (int f = 0; f < 8; f++) {
        int col = 8 * f + 2 * qc;
        float2 bc2 = *(const float2*)(bc + col);
#pragma unroll
        for (int half = 0; half < 2; half++) {
            int rl = rl0 + 8 * half;
            int row = blockIdx.x * 64 + rl;
            float hv0 = Cr[f][2 * half + 0], hv1 = Cr[f][2 * half + 1];
            float c0 = tanhf(Cc[f][2 * half + 0] + bc2.x);
            float c1 = tanhf(Cc[f][2 * half + 1] + bc2.y);
            float u0 = Cu[f][2 * half + 0], u1 = Cu[f][2 * half + 1];
            float o0 = u0 * hv0 + (1.f - u0) * c0;
            float o1 = u1 * hv1 + (1.f - u1) * c1;
            if (row < Nn) *(float2*)(h + (size_t)row * 64 + col) = make_float2(o0, o1);
            U[col * 72 + rl] = f2tf32(o0);
            U[(col + 1) * 72 + rl] = f2tf32(o1);
        }
    }
    __syncwarp();
#pragma unroll
    for (int g = 0; g < 3; g++) {
        float Cq[8][4] = {};
        for (int ch = 0; ch < 2; ch++) {
            unsigned a[4][4];
            load_A_smemU(a, U, rl0, ch * 32, qc);
            mma_gate(Cq, a, g_pkall + (size_t)(PK_QKV + g * 2 + ch) * 2048, lane);
        }
#pragma unroll
        for (int f = 0; f < 8; f++) {
            int col = 8 * f + 2 * qc;
            float2 b2 = *(const float2*)(ipb + g * 64 + col);
            if (v0) *(float2*)(qkvt + (size_t)r0 * 192 + g * 64 + col) =
                make_float2(Cq[f][0] + b2.x, Cq[f][1] + b2.y);
            if (v1) *(float2*)(qkvt + (size_t)r1 * 192 + g * 64 + col) =
                make_float2(Cq[f][2] + b2.x, Cq[f][3] + b2.y);
        }
    }
}

// ---------------- attention tail -------------------------------------------
__global__ __launch_bounds__(128) void k_attn2(
    const float* __restrict__ opb,
    const float* __restrict__ ow, const float* __restrict__ ob,
    float* __restrict__ out) {
    __shared__ float s_qkv[4][Tt * 192];
    __shared__ float s_sc[4][2 * Tt * Tt];
    __shared__ float s_cs[4][2 * Tt];
    __shared__ float s_ob[4][Hh];
    __shared__ float s_ha[4][Hh];
    int w = threadIdx.x >> 5, lane = threadIdx.x & 31;
    int n = blockIdx.x * 4 + w;
    if (n >= Nn) return;
    float* qkv = s_qkv[w];
    float* sc = s_sc[w];
    float* cs = s_cs[w];
    float* obw = s_ob[w];
    float* haw = s_ha[w];

    for (int i = lane; i < Tt * 48; i += 32) {
        int t = i / 48, r = i % 48;
        *(float4*)&qkv[t * 192 + r * 4] =
            *(const float4*)&g_qkv[((size_t)t * Nn + n) * 192 + r * 4];
    }
    __syncwarp();
    for (int idx = lane; idx < 2 * Tt * Tt; idx += 32) {
        int hd = idx / (Tt * Tt);
        int r = idx % (Tt * Tt);
        int t = r / Tt, s = r % Tt;
        const float* qp = &qkv[t * 192 + hd * 32];
        const float* kp = &qkv[s * 192 + 64 + hd * 32];
        float a = 0.f;
#pragma unroll
        for (int d = 0; d < 32; d++) a += qp[d] * kp[d];
        sc[idx] = a * 0.17677669529663687f;
    }
    __syncwarp();
    if (lane < 2 * Tt) {
        float* row = &sc[lane * Tt];
        float mx = row[0];
#pragma unroll
        for (int s = 1; s < Tt; s++) mx = fmaxf(mx, row[s]);
        float sum = 0.f;
#pragma unroll
        for (int s = 0; s < Tt; s++) { float e = __expf(row[s] - mx); row[s] = e; sum += e; }
        float inv = 1.0f / sum;
#pragma unroll
        for (int s = 0; s < Tt; s++) row[s] *= inv;
    }
    __syncwarp();
    if (lane < 2 * Tt) {
        int hd = lane / Tt, s = lane % Tt;
        float a = 0.f;
#pragma unroll
        for (int t = 0; t < Tt; t++) a += sc[hd * Tt * Tt + t * Tt + s];
        cs[lane] = a * (1.0f / 12.0f);
    }
    __syncwarp();
    for (int m = 0; m < 2; m++) {
        int j = lane + 32 * m;
        int hd = j >> 5;
        float a = 0.f;
#pragma unroll
        for (int s = 0; s < Tt; s++) a += cs[hd * Tt + s] * qkv[s * 192 + 128 + j];
        obw[j] = a;
    }
    __syncwarp();
    for (int m = 0; m < 2; m++) {
        int i = lane + 32 * m;
        float a = opb[i];
#pragma unroll
        for (int j = 0; j < Hh; j++) a += g_opwT[j * Hh + i] * obw[j];
        haw[i] = a;
    }
    __syncwarp();
    if (lane < OUTD) {
        float a = ob[lane];
#pragma unroll
        for (int i = 0; i < Hh; i++) a += haw[i] * ow[(size_t)i * OUTD + lane];
        out[(size_t)n * OUTD + lane] = a;
    }
}

// ---------------- host ----------------
extern "C" void kernel_launch(void* const* d_in, const int* in_sizes, int n_in,
                              void* d_out, int out_size) {
    (void)in_sizes; (void)n_in; (void)out_size;
    const float* x   = (const float*)d_in[0];
    const int*   ei  = (const int*)d_in[1];
    const float* ea  = (const float*)d_in[2];
    const float* Wg0 = (const float*)d_in[3];
    const float* bg0 = (const float*)d_in[4];
    const float* Wu0 = (const float*)d_in[5];
    const float* bu0 = (const float*)d_in[6];
    const float* Wr0 = (const float*)d_in[7];
    const float* br0 = (const float*)d_in[8];
    const float* Wc0 = (const float*)d_in[9];
    const float* bc0 = (const float*)d_in[10];
    const float* Wg1 = (const float*)d_in[11];
    const float* bg1 = (const float*)d_in[12];
    const float* Wu1 = (const float*)d_in[13];
    const float* bu1 = (const float*)d_in[14];
    const float* Wr1 = (const float*)d_in[15];
    const float* br1 = (const float*)d_in[16];
    const float* Wc1 = (const float*)d_in[17];
    const float* bc1 = (const float*)d_in[18];
    const float* ipw = (const float*)d_in[19];
    const float* ipb = (const float*)d_in[20];
    const float* opw = (const float*)d_in[21];
    const float* opb = (const float*)d_in[22];
    const float* ow  = (const float*)d_in[23];
    const float* ob  = (const float*)d_in[24];
    float* out = (float*)d_out;

    // lazily-created capture plumbing (host objects only; launches per call
    // are identical every call -> deterministic graph)
    static cudaStream_t s1 = nullptr;
    static cudaEvent_t eA[Tt], eC[Tt], e0;
    if (s1 == nullptr) {
        cudaStreamCreateWithFlags(&s1, cudaStreamNonBlocking);
        cudaEventCreateWithFlags(&e0, cudaEventDisableTiming);
        for (int i = 0; i < Tt; i++) {
            cudaEventCreateWithFlags(&eA[i], cudaEventDisableTiming);
            cudaEventCreateWithFlags(&eC[i], cudaEventDisableTiming);
        }
    }

    void *p_deg, *p_cnt, *p_cur, *p_h0a, *p_h0b, *p_h1, *p_qkv;
    void *p_p0all, *p_xwA, *p_xwB, *p_ipwT;
    cudaGetSymbolAddress(&p_deg, g_deg);
    cudaGetSymbolAddress(&p_cnt, g_cnt);
    cudaGetSymbolAddress(&p_cur, g_cur);
    cudaGetSymbolAddress(&p_h0a, g_h0a);
    cudaGetSymbolAddress(&p_h0b, g_h0b);
    cudaGetSymbolAddress(&p_h1, g_h1);
    cudaGetSymbolAddress(&p_qkv, g_qkv);
    cudaGetSymbolAddress(&p_p0all, g_p0all);
    cudaGetSymbolAddress(&p_xwA, g_xwA);
    cudaGetSymbolAddress(&p_xwB, g_xwB);
    cudaGetSymbolAddress(&p_ipwT, g_ipwT);

    cudaMemsetAsync(p_deg, 0, Nn * sizeof(float), 0);
    cudaMemsetAsync(p_cnt, 0, Nn * sizeof(int), 0);
    cudaMemsetAsync(p_cur, 0, Nn * sizeof(int), 0);
    cudaMemsetAsync(p_h0a, 0, (size_t)Nn * Hh * sizeof(float), 0);
    cudaMemsetAsync(p_h1, 0, (size_t)Nn * Hh * sizeof(float), 0);

    k_prep<<<TB0 + TB1 + TB2, 256>>>(x, ipw, opw, ei, ea);
    k_scan<<<1, 1024>>>();
    k_fill<<<(Ee + 255) / 256, 256>>>(ei, ea);

    float* ipwT = (float*)p_ipwT;
    PackTab tab;
    int gi = 0;
    tab.src[gi] = Wg0; tab.ldw[gi++] = 64;
    const float* Ws0[3] = {Wu0, Wr0, Wc0};
    for (int g = 0; g < 3; g++)
        for (int c = 0; c < 3; c++) { tab.src[gi] = Ws0[g] + (size_t)c * 32 * 64; tab.ldw[gi++] = 64; }
    for (int g = 0; g < 3; g++)
        for (int c = 0; c < 2; c++) { tab.src[gi] = Ws0[g] + (size_t)(96 + c * 32) * 64; tab.ldw[gi++] = 64; }
    for (int c = 0; c < 2; c++) { tab.src[gi] = Wg1 + (size_t)c * 32 * 64; tab.ldw[gi++] = 64; }
    const float* Ws1[3] = {Wu1, Wr1, Wc1};
    for (int g = 0; g < 3; g++)
        for (int c = 0; c < 6; c++) { tab.src[gi] = Ws1[g] + (size_t)c * 32 * 64; tab.ldw[gi++] = 64; }
    for (int g = 0; g < 3; g++)
        for (int c = 0; c < 2; c++) { tab.src[gi] = ipwT + g * 64 + (size_t)c * 32 * 192; tab.ldw[gi++] = 192; }
    k_packall<<<(42 * 512 + 255) / 256, 256>>>(tab);

    k_aggx_all<<<(TN + 7) / 8, 256>>>();
    k_pre0m<<<TN / 64, 128>>>(bg0, bu0, br0, bc0);

    const int AGG_GRID = (Nn + 7) / 8;
    float* hA = (float*)p_h0a;
    float* hB = (float*)p_h0b;
    float* h1 = (float*)p_h1;
    float* xwA = (float*)p_xwA;
    float* xwB = (float*)p_xwB;
    const float* p0all = (const float*)p_p0all;
    float* qkv = (float*)p_qkv;

    // A_t: reads hbuf[t&1 ? B : A]... defined as: A_t reads R_t, writes W_t.
    // R_0 = hA (zeros), W_t = (t even ? hB : hA). xw_t = (t even ? xwA : xwB).
    // fork: A_0 on main stream, then side stream runs A_1..A_11.
    k_urc0x<<<GB, 128>>>(p0all, hA, hB, xwA);          // A_0
    cudaEventRecord(e0, 0);
    cudaStreamWaitEvent(s1, e0, 0);

    for (int t = 0; t < Tt; t++) {
        float* h_t  = (t & 1) ? hA : hB;               // W_t (h0 state of step t)
        float* xw_t = (t & 1) ? xwB : xwA;
        if (t >= 1) cudaStreamWaitEvent(0, eA[t], 0);  // B_t needs A_t (side stream)
        if (t + 1 < Tt) {
            if (t >= 1) cudaStreamWaitEvent(s1, eC[t - 1], 0);   // WAR: h0/xw reuse
            float* h_n  = (t & 1) ? hB : hA;           // W_{t+1}
            float* xw_n = (t & 1) ? xwA : xwB;
            k_urc0x<<<GB, 128, 0, s1>>>(p0all + (size_t)(t + 1) * Nn * 192,
                                        h_t, h_n, xw_n);          // A_{t+1}
            cudaEventRecord(eA[t + 1], s1);
        }
        k_gcn_agg<<<AGG_GRID, 256>>>(bg1, xw_t);       // B_t
        k_urc1q<<<GB, 128>>>(h_t, bu1, br1, bc1, ipb, h1,
                             qkv + (size_t)t * Nn * 192);         // C_t
        cudaEventRecord(eC[t], 0);
    }

    k_attn2<<<(Nn + 3) / 4, 128>>>(opb, ow, ob, out);
}